// round 10
// baseline (speedup 1.0000x reference)
#include <cuda_runtime.h>
#include <math.h>

#define NN 100000
#define EE 1600000
#define DH 128
#define DOUT 40
#define BN_EPS 1e-5f
#define SB 512
#define NBLK ((NN + SB - 1) / SB)   // 196

// ---------------- scratch (device globals: allocation-free) ----------------
__device__ float g_bufB[(size_t)NN * DH];   // gemm output h
__device__ float g_bufC[(size_t)NN * DH];   // aggregation output (+bias), next gemm input
__device__ float g_dinv[NN];
__device__ int   g_cnt[NN];
__device__ int   g_fill[NN];
__device__ int   g_rowstart[NN];
__device__ int   g_incl[NN];
__device__ int   g_bsum[NBLK];
__device__ int   g_boff[NBLK];
__device__ int   g_esrc[EE];                // CSR: src sorted by dst
__device__ float g_ew[EE];                  // CSR: edge norm
__device__ float g_colsum[DH];
__device__ float g_colsq[DH];
__device__ float g_scale[DH];
__device__ float g_shift[DH];

// ---------------- CSR build (edge_index is int32) ----------------
__global__ void zero_prep_kernel() {
    int i = blockIdx.x * blockDim.x + threadIdx.x;
    if (i < NN) { g_cnt[i] = 0; g_fill[i] = 0; }
    if (i < DH) { g_colsum[i] = 0.0f; g_colsq[i] = 0.0f; }
}

__global__ void count_kernel(const int* __restrict__ ei) {
    int e = blockIdx.x * blockDim.x + threadIdx.x;
    if (e >= EE) return;
    int d = ei[EE + e];
    if ((unsigned)d < NN) atomicAdd(&g_cnt[d], 1);
}

__global__ void dinv_kernel() {
    int i = blockIdx.x * blockDim.x + threadIdx.x;
    if (i >= NN) return;
    g_dinv[i] = rsqrtf((float)g_cnt[i] + 1.0f);
}

__global__ void scan_block_kernel() {
    __shared__ int sm[SB];
    int i = blockIdx.x * SB + threadIdx.x;
    int v = (i < NN) ? g_cnt[i] : 0;
    sm[threadIdx.x] = v;
    __syncthreads();
#pragma unroll
    for (int off = 1; off < SB; off <<= 1) {
        int t = (threadIdx.x >= off) ? sm[threadIdx.x - off] : 0;
        __syncthreads();
        sm[threadIdx.x] += t;
        __syncthreads();
    }
    if (i < NN) g_incl[i] = sm[threadIdx.x];
    if (threadIdx.x == SB - 1) g_bsum[blockIdx.x] = sm[SB - 1];
}

__global__ void scan_bsum_kernel() {
    __shared__ int sm[256];
    int v = (threadIdx.x < NBLK) ? g_bsum[threadIdx.x] : 0;
    sm[threadIdx.x] = v;
    __syncthreads();
#pragma unroll
    for (int off = 1; off < 256; off <<= 1) {
        int t = (threadIdx.x >= off) ? sm[threadIdx.x - off] : 0;
        __syncthreads();
        sm[threadIdx.x] += t;
        __syncthreads();
    }
    if (threadIdx.x < NBLK) g_boff[threadIdx.x] = sm[threadIdx.x] - v;
}

__global__ void scan_finalize_kernel() {
    int i = blockIdx.x * blockDim.x + threadIdx.x;
    if (i >= NN) return;
    g_rowstart[i] = g_incl[i] + g_boff[i / SB] - g_cnt[i];
}

__global__ void fill_kernel(const int* __restrict__ ei) {
    int e = blockIdx.x * blockDim.x + threadIdx.x;
    if (e >= EE) return;
    int s = ei[e];
    int d = ei[EE + e];
    if ((unsigned)s >= NN || (unsigned)d >= NN) return;
    int pos = g_rowstart[d] + atomicAdd(&g_fill[d], 1);
    g_esrc[pos] = s;
    g_ew[pos] = g_dinv[s] * g_dinv[d];
}

// ---------------- GEMM 128x128: C[M,128] = act(A)[M,128] @ W[128,128] ----------------
// BM=128, BN=128, BK=16, 256 threads, 8x8 register tile.
// FUSE: A element (row, col) -> relu(A*scale[col]+shift[col])  (BN+ReLU of prev layer)
template<bool FUSE>
__global__ void gemm128_kernel(const float* __restrict__ A, const float* __restrict__ W,
                               float* __restrict__ C, int M) {
    __shared__ float As[16][128];
    __shared__ float Bs[16][128];

    int t = threadIdx.x;
    int trow = t >> 4;          // 0..15
    int tcol = t & 15;          // 0..15
    int rowBase = blockIdx.y * 128;

    int arow = t >> 1;          // 0..127
    int acol = (t & 1) * 8;     // 0 or 8
    int brow = t >> 4;          // 0..15
    int bcol = (t & 15) * 8;    // 0..120

    float acc[8][8];
#pragma unroll
    for (int i = 0; i < 8; i++)
#pragma unroll
        for (int j = 0; j < 8; j++) acc[i][j] = 0.0f;

    for (int k0 = 0; k0 < 128; k0 += 16) {
        // ---- load A tile (transpose into smem), optional BN+ReLU fuse ----
        int gr = rowBase + arow;
        float av[8];
        if (gr < M) {
            float4 a0 = *(const float4*)&A[(size_t)gr * 128 + k0 + acol];
            float4 a1 = *(const float4*)&A[(size_t)gr * 128 + k0 + acol + 4];
            av[0] = a0.x; av[1] = a0.y; av[2] = a0.z; av[3] = a0.w;
            av[4] = a1.x; av[5] = a1.y; av[6] = a1.z; av[7] = a1.w;
        } else {
#pragma unroll
            for (int i = 0; i < 8; i++) av[i] = 0.0f;
        }
        if (FUSE) {
#pragma unroll
            for (int i = 0; i < 8; i++) {
                int col = k0 + acol + i;
                av[i] = fmaxf(av[i] * g_scale[col] + g_shift[col], 0.0f);
            }
        }
#pragma unroll
        for (int i = 0; i < 8; i++) As[acol + i][arow] = av[i];

        // ---- load B tile ----
        {
            float4 b0 = *(const float4*)&W[(size_t)(k0 + brow) * 128 + bcol];
            float4 b1 = *(const float4*)&W[(size_t)(k0 + brow) * 128 + bcol + 4];
            *(float4*)&Bs[brow][bcol]     = b0;
            *(float4*)&Bs[brow][bcol + 4] = b1;
        }
        __syncthreads();

#pragma unroll
        for (int k = 0; k < 16; k++) {
            float a[8], b[8];
            *(float4*)&a[0] = *(const float4*)&As[k][trow * 8];
            *(float4*)&a[4] = *(const float4*)&As[k][trow * 8 + 4];
            *(float4*)&b[0] = *(const float4*)&Bs[k][tcol * 8];
            *(float4*)&b[4] = *(const float4*)&Bs[k][tcol * 8 + 4];
#pragma unroll
            for (int i = 0; i < 8; i++)
#pragma unroll
                for (int j = 0; j < 8; j++) acc[i][j] += a[i] * b[j];
        }
        __syncthreads();
    }

#pragma unroll
    for (int i = 0; i < 8; i++) {
        int gr = rowBase + trow * 8 + i;
        if (gr >= M) continue;
        float* Crow = &C[(size_t)gr * 128 + tcol * 8];
        float4 c0 = make_float4(acc[i][0], acc[i][1], acc[i][2], acc[i][3]);
        float4 c1 = make_float4(acc[i][4], acc[i][5], acc[i][6], acc[i][7]);
        *(float4*)&Crow[0] = c0;
        *(float4*)&Crow[4] = c1;
    }
}

// ---------------- GEMM 128x40: C[M,40] = act(A)[M,128] @ W[128,40] ----------------
// BM=128, 256 threads = 32 trow x 8 tcol; TM=4 rows, TN=5 cols per thread.
__global__ void gemm40_kernel(const float* __restrict__ A, const float* __restrict__ W,
                              float* __restrict__ C, int M) {
    __shared__ float As[16][128];
    __shared__ float Bs[16][40];

    int t = threadIdx.x;
    int trow = t >> 3;          // 0..31
    int tcol = t & 7;           // 0..7
    int rowBase = blockIdx.y * 128;

    int arow = t >> 1;
    int acol = (t & 1) * 8;

    float acc[4][5];
#pragma unroll
    for (int i = 0; i < 4; i++)
#pragma unroll
        for (int j = 0; j < 5; j++) acc[i][j] = 0.0f;

    for (int k0 = 0; k0 < 128; k0 += 16) {
        int gr = rowBase + arow;
        float av[8];
        if (gr < M) {
            float4 a0 = *(const float4*)&A[(size_t)gr * 128 + k0 + acol];
            float4 a1 = *(const float4*)&A[(size_t)gr * 128 + k0 + acol + 4];
            av[0] = a0.x; av[1] = a0.y; av[2] = a0.z; av[3] = a0.w;
            av[4] = a1.x; av[5] = a1.y; av[6] = a1.z; av[7] = a1.w;
        } else {
#pragma unroll
            for (int i = 0; i < 8; i++) av[i] = 0.0f;
        }
#pragma unroll
        for (int i = 0; i < 8; i++) {
            int col = k0 + acol + i;
            av[i] = fmaxf(av[i] * g_scale[col] + g_shift[col], 0.0f);
            As[acol + i][arow] = av[i];
        }
        if (t < 160) {
            int brow = t / 10;
            int bcol = (t % 10) * 4;
            *(float4*)&Bs[brow][bcol] = *(const float4*)&W[(size_t)(k0 + brow) * 40 + bcol];
        }
        __syncthreads();

#pragma unroll
        for (int k = 0; k < 16; k++) {
            float a[4], b[5];
            *(float4*)&a[0] = *(const float4*)&As[k][trow * 4];
#pragma unroll
            for (int j = 0; j < 5; j++) b[j] = Bs[k][tcol * 5 + j];
#pragma unroll
            for (int i = 0; i < 4; i++)
#pragma unroll
                for (int j = 0; j < 5; j++) acc[i][j] += a[i] * b[j];
        }
        __syncthreads();
    }

#pragma unroll
    for (int i = 0; i < 4; i++) {
        int gr = rowBase + trow * 4 + i;
        if (gr >= M) continue;
#pragma unroll
        for (int j = 0; j < 5; j++) C[(size_t)gr * 40 + tcol * 5 + j] = acc[i][j];
    }
}

// ---------------- fused aggregate (D=128): gather + self-loop + bias + BN stats ----------------
// 256 threads = 8 warps; each warp processes 8 nodes; block covers 64 nodes.
__global__ void aggregate128_fused_kernel(const float* __restrict__ H, float* __restrict__ C,
                                          const float* __restrict__ bias) {
    __shared__ float sred[8][256];   // per-warp: [0..127] sum, [128..255] sumsq

    int t = threadIdx.x;
    int w = t >> 5;
    int lane = t & 31;
    const float4* H4 = (const float4*)H;
    float4* C4 = (float4*)C;
    float4 b4 = ((const float4*)bias)[lane];

    float4 ssum = make_float4(0.f, 0.f, 0.f, 0.f);
    float4 ssq  = make_float4(0.f, 0.f, 0.f, 0.f);

    int nodeBase = blockIdx.x * 64 + w * 8;
#pragma unroll 1
    for (int nn = 0; nn < 8; nn++) {
        int node = nodeBase + nn;
        if (node >= NN) break;
        int start = g_rowstart[node];
        int end   = start + g_cnt[node];
        float4 acc = make_float4(0.f, 0.f, 0.f, 0.f);
        int j = start;
        for (; j + 1 < end; j += 2) {
            int   s0 = g_esrc[j],  s1 = g_esrc[j + 1];
            float w0 = g_ew[j],    w1 = g_ew[j + 1];
            float4 h0 = H4[(size_t)s0 * 32 + lane];
            float4 h1 = H4[(size_t)s1 * 32 + lane];
            acc.x += h0.x * w0; acc.y += h0.y * w0; acc.z += h0.z * w0; acc.w += h0.w * w0;
            acc.x += h1.x * w1; acc.y += h1.y * w1; acc.z += h1.z * w1; acc.w += h1.w * w1;
        }
        if (j < end) {
            int s = g_esrc[j]; float ww = g_ew[j];
            float4 h = H4[(size_t)s * 32 + lane];
            acc.x += h.x * ww; acc.y += h.y * ww; acc.z += h.z * ww; acc.w += h.w * ww;
        }
        float di = g_dinv[node];
        float dii = di * di;
        float4 hs = H4[(size_t)node * 32 + lane];
        float4 v = make_float4(acc.x + hs.x * dii + b4.x,
                               acc.y + hs.y * dii + b4.y,
                               acc.z + hs.z * dii + b4.z,
                               acc.w + hs.w * dii + b4.w);
        C4[(size_t)node * 32 + lane] = v;
        ssum.x += v.x; ssum.y += v.y; ssum.z += v.z; ssum.w += v.w;
        ssq.x += v.x * v.x; ssq.y += v.y * v.y; ssq.z += v.z * v.z; ssq.w += v.w * v.w;
    }

    *(float4*)&sred[w][lane * 4]       = ssum;
    *(float4*)&sred[w][128 + lane * 4] = ssq;
    __syncthreads();

    float tot = 0.0f;
#pragma unroll
    for (int ww = 0; ww < 8; ww++) tot += sred[ww][t];
    if (t < 128) atomicAdd(&g_colsum[t], tot);
    else         atomicAdd(&g_colsq[t - 128], tot);
}

__global__ void bn_prep_kernel(const float* __restrict__ g, const float* __restrict__ be) {
    int f = threadIdx.x;
    if (f >= DH) return;
    float mu  = g_colsum[f] / (float)NN;
    float var = g_colsq[f] / (float)NN - mu * mu;
    float sc  = g[f] * rsqrtf(var + BN_EPS);
    g_scale[f] = sc;
    g_shift[f] = be[f] - mu * sc;
    g_colsum[f] = 0.0f;   // reset for next layer's aggregate
    g_colsq[f]  = 0.0f;
}

// ---------------- fused layer-3: aggregate (D=40) + self + bias + log-softmax ----------------
// Warp per node; lanes 0..9 hold float4 features.
__global__ void aggregate40_softmax_kernel(const float* __restrict__ H,
                                           const float* __restrict__ bf,
                                           float* __restrict__ out) {
    int warp = (blockIdx.x * blockDim.x + threadIdx.x) >> 5;
    int lane = threadIdx.x & 31;
    if (warp >= NN) return;
    int start = g_rowstart[warp];
    int end   = start + g_cnt[warp];
    const float4* H4 = (const float4*)H;
    bool act = lane < 10;

    float4 acc = make_float4(0.f, 0.f, 0.f, 0.f);
    for (int j = start; j < end; j++) {
        int s = g_esrc[j]; float ww = g_ew[j];
        if (act) {
            float4 h = H4[(size_t)s * 10 + lane];
            acc.x += h.x * ww; acc.y += h.y * ww; acc.z += h.z * ww; acc.w += h.w * ww;
        }
    }
    float4 v = make_float4(-1e30f, -1e30f, -1e30f, -1e30f);
    if (act) {
        float di = g_dinv[warp];
        float dii = di * di;
        float4 hs = H4[(size_t)warp * 10 + lane];
        float4 b4 = ((const float4*)bf)[lane];
        v = make_float4(acc.x + hs.x * dii + b4.x,
                        acc.y + hs.y * dii + b4.y,
                        acc.z + hs.z * dii + b4.z,
                        acc.w + hs.w * dii + b4.w);
    }

    float m = fmaxf(fmaxf(v.x, v.y), fmaxf(v.z, v.w));
#pragma unroll
    for (int o = 16; o > 0; o >>= 1) m = fmaxf(m, __shfl_xor_sync(0xffffffffu, m, o));

    float s = 0.0f;
    if (act) s = expf(v.x - m) + expf(v.y - m) + expf(v.z - m) + expf(v.w - m);
#pragma unroll
    for (int o = 16; o > 0; o >>= 1) s += __shfl_xor_sync(0xffffffffu, s, o);

    float ls = m + logf(s);
    if (act) {
        float4 r = make_float4(v.x - ls, v.y - ls, v.z - ls, v.w - ls);
        ((float4*)out)[(size_t)warp * 10 + lane] = r;
    }
}

// ---------------- host launch ----------------
extern "C" void kernel_launch(void* const* d_in, const int* in_sizes, int n_in,
                              void* d_out, int out_size) {
    const float* x   = (const float*)d_in[0];
    const int*   ei  = (const int*)d_in[1];    // int32 edge_index
    const float* W1  = (const float*)d_in[2];
    const float* b1  = (const float*)d_in[3];
    const float* g1  = (const float*)d_in[4];
    const float* be1 = (const float*)d_in[5];
    const float* W2  = (const float*)d_in[6];
    const float* b2  = (const float*)d_in[7];
    const float* g2  = (const float*)d_in[8];
    const float* be2 = (const float*)d_in[9];
    const float* Wf  = (const float*)d_in[10];
    const float* bf  = (const float*)d_in[11];
    float* out = (float*)d_out;

    float *bufB, *bufC;
    cudaGetSymbolAddress((void**)&bufB, g_bufB);
    cudaGetSymbolAddress((void**)&bufC, g_bufC);

    const int T = 256;
    const int nBlocksN = (NN + T - 1) / T;
    const int nBlocksE = (EE + T - 1) / T;

    // --- CSR build ---
    zero_prep_kernel<<<nBlocksN, T>>>();
    count_kernel<<<nBlocksE, T>>>(ei);
    dinv_kernel<<<nBlocksN, T>>>();
    scan_block_kernel<<<NBLK, SB>>>();
    scan_bsum_kernel<<<1, 256>>>();
    scan_finalize_kernel<<<nBlocksN, T>>>();
    fill_kernel<<<nBlocksE, T>>>(ei);

    dim3 gemmGrid(1, (NN + 127) / 128);       // 782
    const int aggBlocks = (NN + 63) / 64;     // 1563 (64 nodes per block)
    const int agg40Blocks = (NN * 32 + T - 1) / T;

    // ---------------- layer 1 ----------------
    gemm128_kernel<false><<<gemmGrid, T>>>(x, W1, bufB, NN);
    aggregate128_fused_kernel<<<aggBlocks, T>>>(bufB, bufC, b1);
    bn_prep_kernel<<<1, 128>>>(g1, be1);

    // ---------------- layer 2 (BN+ReLU fused into A-load) ----------------
    gemm128_kernel<true><<<gemmGrid, T>>>(bufC, W2, bufB, NN);
    aggregate128_fused_kernel<<<aggBlocks, T>>>(bufB, bufC, b2);
    bn_prep_kernel<<<1, 128>>>(g2, be2);

    // ---------------- layer 3 (BN+ReLU fused; aggregate+softmax fused) ----------------
    gemm40_kernel<<<gemmGrid, T>>>(bufC, Wf, bufB, NN);
    aggregate40_softmax_kernel<<<agg40Blocks, T>>>(bufB, bf, out);
}

// round 11
// speedup vs baseline: 1.2897x; 1.2897x over previous
#include <cuda_runtime.h>
#include <math.h>

#define NN 100000
#define EE 1600000
#define DH 128
#define DOUT 40
#define BN_EPS 1e-5f
#define SB 512
#define NBLK ((NN + SB - 1) / SB)   // 196

// ---------------- scratch (device globals: allocation-free) ----------------
// NOTE: g_cnt/g_fill rely on static zero-init for the FIRST execution; the
// final kernel of every execution re-zeroes them, so every graph replay sees
// zeroed counters. g_colsum/g_colsq likewise (bn_prep resets after use).
__device__ float g_bufB[(size_t)NN * DH];   // gemm output h
__device__ float g_bufC[(size_t)NN * DH];   // aggregated output (+bias), next gemm input
__device__ float g_dinv[NN];
__device__ int   g_cnt[NN];
__device__ int   g_fill[NN];
__device__ int   g_rowstart[NN];
__device__ int   g_incl[NN];
__device__ int   g_bsum[NBLK];
__device__ int   g_boff[NBLK];
__device__ int   g_esrc[EE];                // CSR: src sorted by dst
__device__ float g_ew[EE];                  // CSR: edge norm
__device__ float g_colsum[DH];
__device__ float g_colsq[DH];
__device__ float g_scale[DH];
__device__ float g_shift[DH];

// ---------------- CSR build (edge_index is int32) ----------------
// launch 0
__global__ void count_kernel(const int* __restrict__ ei) {
    int e = blockIdx.x * blockDim.x + threadIdx.x;
    if (e >= EE) return;
    int d = ei[EE + e];
    if ((unsigned)d < NN) atomicAdd(&g_cnt[d], 1);
}

// launch 1: inclusive scan within 512-blocks, also computes dinv
__global__ void scan_block_kernel() {
    __shared__ int sm[SB];
    int i = blockIdx.x * SB + threadIdx.x;
    int v = (i < NN) ? g_cnt[i] : 0;
    if (i < NN) g_dinv[i] = rsqrtf((float)v + 1.0f);
    sm[threadIdx.x] = v;
    __syncthreads();
#pragma unroll
    for (int off = 1; off < SB; off <<= 1) {
        int t = (threadIdx.x >= off) ? sm[threadIdx.x - off] : 0;
        __syncthreads();
        sm[threadIdx.x] += t;
        __syncthreads();
    }
    if (i < NN) g_incl[i] = sm[threadIdx.x];
    if (threadIdx.x == SB - 1) g_bsum[blockIdx.x] = sm[SB - 1];
}

// launch 2
__global__ void scan_bsum_kernel() {
    __shared__ int sm[256];
    int v = (threadIdx.x < NBLK) ? g_bsum[threadIdx.x] : 0;
    sm[threadIdx.x] = v;
    __syncthreads();
#pragma unroll
    for (int off = 1; off < 256; off <<= 1) {
        int t = (threadIdx.x >= off) ? sm[threadIdx.x - off] : 0;
        __syncthreads();
        sm[threadIdx.x] += t;
        __syncthreads();
    }
    if (threadIdx.x < NBLK) g_boff[threadIdx.x] = sm[threadIdx.x] - v;
}

// launch 3
__global__ void scan_finalize_kernel() {
    int i = blockIdx.x * blockDim.x + threadIdx.x;
    if (i >= NN) return;
    g_rowstart[i] = g_incl[i] + g_boff[i / SB] - g_cnt[i];
}

// launch 4
__global__ void fill_kernel(const int* __restrict__ ei) {
    int e = blockIdx.x * blockDim.x + threadIdx.x;
    if (e >= EE) return;
    int s = ei[e];
    int d = ei[EE + e];
    if ((unsigned)s >= NN || (unsigned)d >= NN) return;
    int pos = g_rowstart[d] + atomicAdd(&g_fill[d], 1);
    g_esrc[pos] = s;
    g_ew[pos] = g_dinv[s] * g_dinv[d];
}

// ---------------- GEMM 128x128: C[M,128] = act(A)[M,128] @ W[128,128] ----------------
// launch 5 (layer 1) -- ncu -s 5 captures this.
// BM=128, BN=128, BK=16, 256 threads, 8x8 register tile.
template<bool FUSE>
__global__ void __launch_bounds__(256, 2)
gemm128_kernel(const float* __restrict__ A, const float* __restrict__ W,
               float* __restrict__ C, int M) {
    __shared__ float As[16][128];
    __shared__ float Bs[16][128];

    int t = threadIdx.x;
    int trow = t >> 4;          // 0..15
    int tcol = t & 15;          // 0..15
    int rowBase = blockIdx.y * 128;

    int arow = t >> 1;          // 0..127
    int acol = (t & 1) * 8;     // 0 or 8
    int brow = t >> 4;          // 0..15
    int bcol = (t & 15) * 8;    // 0..120

    float acc[8][8];
#pragma unroll
    for (int i = 0; i < 8; i++)
#pragma unroll
        for (int j = 0; j < 8; j++) acc[i][j] = 0.0f;

    for (int k0 = 0; k0 < 128; k0 += 16) {
        int gr = rowBase + arow;
        float av[8];
        if (gr < M) {
            float4 a0 = *(const float4*)&A[(size_t)gr * 128 + k0 + acol];
            float4 a1 = *(const float4*)&A[(size_t)gr * 128 + k0 + acol + 4];
            av[0] = a0.x; av[1] = a0.y; av[2] = a0.z; av[3] = a0.w;
            av[4] = a1.x; av[5] = a1.y; av[6] = a1.z; av[7] = a1.w;
        } else {
#pragma unroll
            for (int i = 0; i < 8; i++) av[i] = 0.0f;
        }
        if (FUSE) {
#pragma unroll
            for (int i = 0; i < 8; i++) {
                int col = k0 + acol + i;
                av[i] = fmaxf(av[i] * g_scale[col] + g_shift[col], 0.0f);
            }
        }
#pragma unroll
        for (int i = 0; i < 8; i++) As[acol + i][arow] = av[i];

        {
            float4 b0 = *(const float4*)&W[(size_t)(k0 + brow) * 128 + bcol];
            float4 b1 = *(const float4*)&W[(size_t)(k0 + brow) * 128 + bcol + 4];
            *(float4*)&Bs[brow][bcol]     = b0;
            *(float4*)&Bs[brow][bcol + 4] = b1;
        }
        __syncthreads();

#pragma unroll
        for (int k = 0; k < 16; k++) {
            float a[8], b[8];
            *(float4*)&a[0] = *(const float4*)&As[k][trow * 8];
            *(float4*)&a[4] = *(const float4*)&As[k][trow * 8 + 4];
            *(float4*)&b[0] = *(const float4*)&Bs[k][tcol * 8];
            *(float4*)&b[4] = *(const float4*)&Bs[k][tcol * 8 + 4];
#pragma unroll
            for (int i = 0; i < 8; i++)
#pragma unroll
                for (int j = 0; j < 8; j++) acc[i][j] += a[i] * b[j];
        }
        __syncthreads();
    }

#pragma unroll
    for (int i = 0; i < 8; i++) {
        int gr = rowBase + trow * 8 + i;
        if (gr >= M) continue;
        float* Crow = &C[(size_t)gr * 128 + tcol * 8];
        *(float4*)&Crow[0] = make_float4(acc[i][0], acc[i][1], acc[i][2], acc[i][3]);
        *(float4*)&Crow[4] = make_float4(acc[i][4], acc[i][5], acc[i][6], acc[i][7]);
    }
}

// ---------------- GEMM 128x40 with fused BN+ReLU on A ----------------
__global__ void __launch_bounds__(256, 4)
gemm40_kernel(const float* __restrict__ A, const float* __restrict__ W,
              float* __restrict__ C, int M) {
    __shared__ float As[16][128];
    __shared__ float Bs[16][40];

    int t = threadIdx.x;
    int trow = t >> 3;          // 0..31
    int tcol = t & 7;           // 0..7
    int rowBase = blockIdx.y * 128;

    int arow = t >> 1;
    int acol = (t & 1) * 8;

    float acc[4][5];
#pragma unroll
    for (int i = 0; i < 4; i++)
#pragma unroll
        for (int j = 0; j < 5; j++) acc[i][j] = 0.0f;

    for (int k0 = 0; k0 < 128; k0 += 16) {
        int gr = rowBase + arow;
        float av[8];
        if (gr < M) {
            float4 a0 = *(const float4*)&A[(size_t)gr * 128 + k0 + acol];
            float4 a1 = *(const float4*)&A[(size_t)gr * 128 + k0 + acol + 4];
            av[0] = a0.x; av[1] = a0.y; av[2] = a0.z; av[3] = a0.w;
            av[4] = a1.x; av[5] = a1.y; av[6] = a1.z; av[7] = a1.w;
        } else {
#pragma unroll
            for (int i = 0; i < 8; i++) av[i] = 0.0f;
        }
#pragma unroll
        for (int i = 0; i < 8; i++) {
            int col = k0 + acol + i;
            av[i] = fmaxf(av[i] * g_scale[col] + g_shift[col], 0.0f);
            As[acol + i][arow] = av[i];
        }
        if (t < 160) {
            int brow = t / 10;
            int bcol = (t % 10) * 4;
            *(float4*)&Bs[brow][bcol] = *(const float4*)&W[(size_t)(k0 + brow) * 40 + bcol];
        }
        __syncthreads();

#pragma unroll
        for (int k = 0; k < 16; k++) {
            float a[4], b[5];
            *(float4*)&a[0] = *(const float4*)&As[k][trow * 4];
#pragma unroll
            for (int j = 0; j < 5; j++) b[j] = Bs[k][tcol * 5 + j];
#pragma unroll
            for (int i = 0; i < 4; i++)
#pragma unroll
                for (int j = 0; j < 5; j++) acc[i][j] += a[i] * b[j];
        }
        __syncthreads();
    }

#pragma unroll
    for (int i = 0; i < 4; i++) {
        int gr = rowBase + trow * 4 + i;
        if (gr >= M) continue;
#pragma unroll
        for (int j = 0; j < 5; j++) C[(size_t)gr * 40 + tcol * 5 + j] = acc[i][j];
    }
}

// ---------------- aggregate (D=128): warp per node, self+bias fused ----------------
__global__ void aggregate128_kernel(const float* __restrict__ H, float* __restrict__ C,
                                    const float* __restrict__ bias) {
    int warp = (blockIdx.x * blockDim.x + threadIdx.x) >> 5;
    int lane = threadIdx.x & 31;
    if (warp >= NN) return;
    int start = g_rowstart[warp];
    int end   = start + g_cnt[warp];
    const float4* H4 = (const float4*)H;
    float4 acc = make_float4(0.f, 0.f, 0.f, 0.f);
    int j = start;
    for (; j + 1 < end; j += 2) {
        int   s0 = g_esrc[j],  s1 = g_esrc[j + 1];
        float w0 = g_ew[j],    w1 = g_ew[j + 1];
        float4 h0 = H4[(size_t)s0 * 32 + lane];
        float4 h1 = H4[(size_t)s1 * 32 + lane];
        acc.x += h0.x * w0; acc.y += h0.y * w0; acc.z += h0.z * w0; acc.w += h0.w * w0;
        acc.x += h1.x * w1; acc.y += h1.y * w1; acc.z += h1.z * w1; acc.w += h1.w * w1;
    }
    if (j < end) {
        int s = g_esrc[j]; float w = g_ew[j];
        float4 h = H4[(size_t)s * 32 + lane];
        acc.x += h.x * w; acc.y += h.y * w; acc.z += h.z * w; acc.w += h.w * w;
    }
    float di = g_dinv[warp];
    float dii = di * di;
    float4 hs = H4[(size_t)warp * 32 + lane];
    float4 b4 = ((const float4*)bias)[lane];
    ((float4*)C)[(size_t)warp * 32 + lane] =
        make_float4(acc.x + hs.x * dii + b4.x, acc.y + hs.y * dii + b4.y,
                    acc.z + hs.z * dii + b4.z, acc.w + hs.w * dii + b4.w);
}

// ---------------- BN column stats: read-only pass over C ----------------
__global__ void colstats_kernel(const float* __restrict__ C) {
    int f  = threadIdx.x;            // 0..127
    int r0 = blockIdx.x * 256;
    int r1 = r0 + 256;
    if (r1 > NN) r1 = NN;
    float s = 0.0f, s2 = 0.0f;
    for (int r = r0; r < r1; r++) {
        float v = C[(size_t)r * DH + f];
        s += v;
        s2 += v * v;
    }
    atomicAdd(&g_colsum[f], s);
    atomicAdd(&g_colsq[f], s2);
}

__global__ void bn_prep_kernel(const float* __restrict__ g, const float* __restrict__ be) {
    int f = threadIdx.x;
    if (f >= DH) return;
    float mu  = g_colsum[f] / (float)NN;
    float var = g_colsq[f] / (float)NN - mu * mu;
    float sc  = g[f] * rsqrtf(var + BN_EPS);
    g_scale[f] = sc;
    g_shift[f] = be[f] - mu * sc;
    g_colsum[f] = 0.0f;   // reset for next layer / next execution
    g_colsq[f]  = 0.0f;
}

// ---------------- layer-3: aggregate (D=40) + self + bias + log-softmax ----------------
// Also re-zeroes g_cnt/g_fill for the next graph execution.
__global__ void aggregate40_softmax_kernel(const float* __restrict__ H,
                                           const float* __restrict__ bf,
                                           float* __restrict__ out) {
    int warp = (blockIdx.x * blockDim.x + threadIdx.x) >> 5;
    int lane = threadIdx.x & 31;
    if (warp >= NN) return;
    int start = g_rowstart[warp];
    int end   = start + g_cnt[warp];
    if (lane == 0) { g_cnt[warp] = 0; g_fill[warp] = 0; }   // reset for next run
    const float4* H4 = (const float4*)H;
    bool act = lane < 10;

    float4 acc = make_float4(0.f, 0.f, 0.f, 0.f);
    for (int j = start; j < end; j++) {
        int s = g_esrc[j]; float ww = g_ew[j];
        if (act) {
            float4 h = H4[(size_t)s * 10 + lane];
            acc.x += h.x * ww; acc.y += h.y * ww; acc.z += h.z * ww; acc.w += h.w * ww;
        }
    }
    float4 v = make_float4(-1e30f, -1e30f, -1e30f, -1e30f);
    if (act) {
        float di = g_dinv[warp];
        float dii = di * di;
        float4 hs = H4[(size_t)warp * 10 + lane];
        float4 b4 = ((const float4*)bf)[lane];
        v = make_float4(acc.x + hs.x * dii + b4.x, acc.y + hs.y * dii + b4.y,
                        acc.z + hs.z * dii + b4.z, acc.w + hs.w * dii + b4.w);
    }

    float m = fmaxf(fmaxf(v.x, v.y), fmaxf(v.z, v.w));
#pragma unroll
    for (int o = 16; o > 0; o >>= 1) m = fmaxf(m, __shfl_xor_sync(0xffffffffu, m, o));

    float s = 0.0f;
    if (act) s = expf(v.x - m) + expf(v.y - m) + expf(v.z - m) + expf(v.w - m);
#pragma unroll
    for (int o = 16; o > 0; o >>= 1) s += __shfl_xor_sync(0xffffffffu, s, o);

    float ls = m + logf(s);
    if (act) {
        ((float4*)out)[(size_t)warp * 10 + lane] =
            make_float4(v.x - ls, v.y - ls, v.z - ls, v.w - ls);
    }
}

// ---------------- host launch ----------------
extern "C" void kernel_launch(void* const* d_in, const int* in_sizes, int n_in,
                              void* d_out, int out_size) {
    const float* x   = (const float*)d_in[0];
    const int*   ei  = (const int*)d_in[1];    // int32 edge_index
    const float* W1  = (const float*)d_in[2];
    const float* b1  = (const float*)d_in[3];
    const float* g1  = (const float*)d_in[4];
    const float* be1 = (const float*)d_in[5];
    const float* W2  = (const float*)d_in[6];
    const float* b2  = (const float*)d_in[7];
    const float* g2  = (const float*)d_in[8];
    const float* be2 = (const float*)d_in[9];
    const float* Wf  = (const float*)d_in[10];
    const float* bf  = (const float*)d_in[11];
    float* out = (float*)d_out;

    float *bufB, *bufC;
    cudaGetSymbolAddress((void**)&bufB, g_bufB);
    cudaGetSymbolAddress((void**)&bufC, g_bufC);

    const int T = 256;
    const int nBlocksN = (NN + T - 1) / T;
    const int nBlocksE = (EE + T - 1) / T;

    // --- CSR build: launches 0..4 ---
    count_kernel<<<nBlocksE, T>>>(ei);          // 0
    scan_block_kernel<<<NBLK, SB>>>();          // 1 (also dinv)
    scan_bsum_kernel<<<1, 256>>>();             // 2
    scan_finalize_kernel<<<nBlocksN, T>>>();    // 3
    fill_kernel<<<nBlocksE, T>>>(ei);           // 4

    dim3 gemmGrid(1, (NN + 127) / 128);
    const int warpBlocks = (NN * 32 + T - 1) / T;   // warp per node
    const int statBlocks = (NN + 255) / 256;

    // ---------------- layer 1 ----------------
    gemm128_kernel<false><<<gemmGrid, T>>>(x, W1, bufB, NN);     // 5  <- ncu target
    aggregate128_kernel<<<warpBlocks, T>>>(bufB, bufC, b1);      // 6
    colstats_kernel<<<statBlocks, 128>>>(bufC);                  // 7
    bn_prep_kernel<<<1, 128>>>(g1, be1);                         // 8

    // ---------------- layer 2 ----------------
    gemm128_kernel<true><<<gemmGrid, T>>>(bufC, W2, bufB, NN);   // 9
    aggregate128_kernel<<<warpBlocks, T>>>(bufB, bufC, b2);      // 10
    colstats_kernel<<<statBlocks, 128>>>(bufC);                  // 11
    bn_prep_kernel<<<1, 128>>>(g2, be2);                         // 12

    // ---------------- layer 3 ----------------
    gemm40_kernel<<<gemmGrid, T>>>(bufC, Wf, bufB, NN);          // 13
    aggregate40_softmax_kernel<<<warpBlocks, T>>>(bufB, bf, out);// 14
}

// round 13
// speedup vs baseline: 1.4051x; 1.0895x over previous
#include <cuda_runtime.h>
#include <math.h>
#include <stdint.h>

#define NN 100000
#define EE 1600000
#define DH 128
#define DOUT 40
#define BN_EPS 1e-5f
#define SB 512
#define NBLK ((NN + SB - 1) / SB)   // 196

// mma GEMM smem strides (in floats). AST%32==4 and BST%32==8 make the
// m16n8k8 A/B fragment LDS patterns bank-conflict-free.
#define AST 132
#define BST 136
#define SMEM_GEMM_BYTES ((128 * AST + 128 * BST) * 4)   // 137216

// ---------------- scratch (device globals) ----------------
__device__ float    g_bufB[(size_t)NN * DH];
__device__ float    g_bufC[(size_t)NN * DH];
__device__ uint32_t g_W1t[128 * BST];        // W1 as tf32, [k][n] stride BST
__device__ uint32_t g_W2t[128 * BST];
__device__ float    g_dinv[NN];
__device__ int      g_cnt[NN];
__device__ int      g_fill[NN];
__device__ int      g_rowstart[NN];
__device__ int      g_incl[NN];
__device__ int      g_bsum[NBLK];
__device__ int      g_boff[NBLK];
__device__ int      g_esrc[EE];
__device__ float    g_ew[EE];
__device__ float    g_colsum[DH];
__device__ float    g_colsq[DH];
__device__ float    g_scale[DH];
__device__ float    g_shift[DH];

__device__ __forceinline__ uint32_t cvt_tf32(float f) {
    uint32_t u;
    asm("cvt.rna.tf32.f32 %0, %1;" : "=r"(u) : "f"(f));
    return u;
}

__device__ __forceinline__ void mma_tf32(float* d, const uint32_t* a, uint32_t b0, uint32_t b1) {
    asm volatile(
        "mma.sync.aligned.m16n8k8.row.col.f32.tf32.tf32.f32 "
        "{%0,%1,%2,%3}, {%4,%5,%6,%7}, {%8,%9}, {%0,%1,%2,%3};"
        : "+f"(d[0]), "+f"(d[1]), "+f"(d[2]), "+f"(d[3])
        : "r"(a[0]), "r"(a[1]), "r"(a[2]), "r"(a[3]), "r"(b0), "r"(b1));
}

// ---------------- W precompute: tf32 convert, [k][n] stride BST ----------------
__global__ void prep_w_kernel(const float* __restrict__ W1, const float* __restrict__ W2) {
    int idx = blockIdx.x * blockDim.x + threadIdx.x;
    if (idx >= 32768) return;
    int which = idx >> 14;
    int rem = idx & 16383;
    int k = rem >> 7;
    int n = rem & 127;
    const float* W = which ? W2 : W1;
    uint32_t* dst = which ? g_W2t : g_W1t;
    dst[k * BST + n] = cvt_tf32(W[k * 128 + n]);
}

// ---------------- CSR build (edge_index is int32) ----------------
__global__ void count_kernel(const int* __restrict__ ei) {
    int e = blockIdx.x * blockDim.x + threadIdx.x;
    if (e >= EE) return;
    int d = ei[EE + e];
    if ((unsigned)d < NN) atomicAdd(&g_cnt[d], 1);
}

__global__ void scan_block_kernel() {
    __shared__ int sm[SB];
    int i = blockIdx.x * SB + threadIdx.x;
    int v = (i < NN) ? g_cnt[i] : 0;
    if (i < NN) g_dinv[i] = rsqrtf((float)v + 1.0f);
    sm[threadIdx.x] = v;
    __syncthreads();
#pragma unroll
    for (int off = 1; off < SB; off <<= 1) {
        int t = (threadIdx.x >= off) ? sm[threadIdx.x - off] : 0;
        __syncthreads();
        sm[threadIdx.x] += t;
        __syncthreads();
    }
    if (i < NN) g_incl[i] = sm[threadIdx.x];
    if (threadIdx.x == SB - 1) g_bsum[blockIdx.x] = sm[SB - 1];
}

__global__ void scan_bsum_kernel() {
    __shared__ int sm[256];
    int v = (threadIdx.x < NBLK) ? g_bsum[threadIdx.x] : 0;
    sm[threadIdx.x] = v;
    __syncthreads();
#pragma unroll
    for (int off = 1; off < 256; off <<= 1) {
        int t = (threadIdx.x >= off) ? sm[threadIdx.x - off] : 0;
        __syncthreads();
        sm[threadIdx.x] += t;
        __syncthreads();
    }
    if (threadIdx.x < NBLK) g_boff[threadIdx.x] = sm[threadIdx.x] - v;
}

__global__ void scan_finalize_kernel() {
    int i = blockIdx.x * blockDim.x + threadIdx.x;
    if (i >= NN) return;
    g_rowstart[i] = g_incl[i] + g_boff[i / SB] - g_cnt[i];
}

__global__ void fill_kernel(const int* __restrict__ ei) {
    int e = blockIdx.x * blockDim.x + threadIdx.x;
    if (e >= EE) return;
    int s = ei[e];
    int d = ei[EE + e];
    if ((unsigned)s >= NN || (unsigned)d >= NN) return;
    int pos = g_rowstart[d] + atomicAdd(&g_fill[d], 1);
    g_esrc[pos] = s;
    g_ew[pos] = g_dinv[s] * g_dinv[d];
}

// ---------------- TF32 mma.sync GEMM: C[M,128] = act(A)[M,128] @ W ----------------
// 256 threads = 8 warps (4 on M x 2 on N); warp computes 32x64 via m16n8k8.
template<bool FUSE>
__global__ void __launch_bounds__(256, 1)
gemm_mma_kernel(const float* __restrict__ A, const uint32_t* __restrict__ Wt,
                float* __restrict__ C, int M) {
    extern __shared__ uint32_t smu[];
    uint32_t* sA = smu;                  // [128][AST]
    uint32_t* sBm = smu + 128 * AST;     // [128][BST]

    int t = threadIdx.x;
    int lane = t & 31;
    int wid = t >> 5;
    int warpM = wid & 3;
    int warpN = wid >> 2;
    int rowBase = blockIdx.x * 128;

    // ---- B tile: linear copy of pre-converted W (incl. pad) ----
    {
        const uint4* g = (const uint4*)Wt;
        uint4* d = (uint4*)sBm;
        for (int i = t; i < (128 * BST) / 4; i += 256) d[i] = g[i];
    }

    // ---- A tile: row-major load, tf32 convert (+BN/ReLU fuse) ----
    {
        int row = t >> 1;
        int half = t & 1;
        int gr = rowBase + row;
        const float4* Ar = (const float4*)(A + (size_t)gr * 128 + half * 64);
        uint32_t* dst = sA + row * AST + half * 64;
#pragma unroll
        for (int i = 0; i < 16; i++) {
            float4 v = (gr < M) ? Ar[i] : make_float4(0.f, 0.f, 0.f, 0.f);
            if (FUSE) {
                int col = half * 64 + i * 4;
                v.x = fmaxf(v.x * g_scale[col + 0] + g_shift[col + 0], 0.0f);
                v.y = fmaxf(v.y * g_scale[col + 1] + g_shift[col + 1], 0.0f);
                v.z = fmaxf(v.z * g_scale[col + 2] + g_shift[col + 2], 0.0f);
                v.w = fmaxf(v.w * g_scale[col + 3] + g_shift[col + 3], 0.0f);
            }
            *(uint4*)(dst + i * 4) =
                make_uint4(cvt_tf32(v.x), cvt_tf32(v.y), cvt_tf32(v.z), cvt_tf32(v.w));
        }
    }
    __syncthreads();

    float acc[2][8][4];
#pragma unroll
    for (int mi = 0; mi < 2; mi++)
#pragma unroll
        for (int nj = 0; nj < 8; nj++)
#pragma unroll
            for (int q = 0; q < 4; q++) acc[mi][nj][q] = 0.0f;

    int ar = warpM * 32 + (lane >> 2);   // A fragment row (groupID)
    int ac = lane & 3;                   // A fragment col (k within step)
    int bn = warpN * 64 + (lane >> 2);   // B fragment col (n)
    int bk = lane & 3;                   // B fragment row (k within step)

#pragma unroll 4
    for (int k0 = 0; k0 < 128; k0 += 8) {
        uint32_t a[2][4];
#pragma unroll
        for (int mi = 0; mi < 2; mi++) {
            const uint32_t* p = sA + (ar + mi * 16) * AST + k0 + ac;
            a[mi][0] = p[0];
            a[mi][1] = p[8 * AST];
            a[mi][2] = p[4];
            a[mi][3] = p[8 * AST + 4];
        }
#pragma unroll
        for (int nj = 0; nj < 8; nj++) {
            const uint32_t* q = sBm + (k0 + bk) * BST + bn + nj * 8;
            uint32_t b0 = q[0];
            uint32_t b1 = q[4 * BST];
            mma_tf32(acc[0][nj], a[0], b0, b1);
            mma_tf32(acc[1][nj], a[1], b0, b1);
        }
    }

    // ---- store C ----
#pragma unroll
    for (int mi = 0; mi < 2; mi++) {
        int r0 = rowBase + warpM * 32 + mi * 16 + (lane >> 2);
        int r1 = r0 + 8;
#pragma unroll
        for (int nj = 0; nj < 8; nj++) {
            int col = warpN * 64 + nj * 8 + 2 * (lane & 3);
            if (r0 < M)
                *(float2*)&C[(size_t)r0 * 128 + col] = make_float2(acc[mi][nj][0], acc[mi][nj][1]);
            if (r1 < M)
                *(float2*)&C[(size_t)r1 * 128 + col] = make_float2(acc[mi][nj][2], acc[mi][nj][3]);
        }
    }
}

// ---------------- GEMM 128x40 fp32 with fused BN+ReLU on A ----------------
__global__ void __launch_bounds__(256, 4)
gemm40_kernel(const float* __restrict__ A, const float* __restrict__ W,
              float* __restrict__ C, int M) {
    __shared__ float As[16][128];
    __shared__ float Bs[16][40];

    int t = threadIdx.x;
    int trow = t >> 3;
    int tcol = t & 7;
    int rowBase = blockIdx.y * 128;

    int arow = t >> 1;
    int acol = (t & 1) * 8;

    float acc[4][5];
#pragma unroll
    for (int i = 0; i < 4; i++)
#pragma unroll
        for (int j = 0; j < 5; j++) acc[i][j] = 0.0f;

    for (int k0 = 0; k0 < 128; k0 += 16) {
        int gr = rowBase + arow;
        float av[8];
        if (gr < M) {
            float4 a0 = *(const float4*)&A[(size_t)gr * 128 + k0 + acol];
            float4 a1 = *(const float4*)&A[(size_t)gr * 128 + k0 + acol + 4];
            av[0] = a0.x; av[1] = a0.y; av[2] = a0.z; av[3] = a0.w;
            av[4] = a1.x; av[5] = a1.y; av[6] = a1.z; av[7] = a1.w;
        } else {
#pragma unroll
            for (int i = 0; i < 8; i++) av[i] = 0.0f;
        }
#pragma unroll
        for (int i = 0; i < 8; i++) {
            int col = k0 + acol + i;
            av[i] = fmaxf(av[i] * g_scale[col] + g_shift[col], 0.0f);
            As[acol + i][arow] = av[i];
        }
        if (t < 160) {
            int brow = t / 10;
            int bcol = (t % 10) * 4;
            *(float4*)&Bs[brow][bcol] = *(const float4*)&W[(size_t)(k0 + brow) * 40 + bcol];
        }
        __syncthreads();

#pragma unroll
        for (int k = 0; k < 16; k++) {
            float a[4], b[5];
            *(float4*)&a[0] = *(const float4*)&As[k][trow * 4];
#pragma unroll
            for (int j = 0; j < 5; j++) b[j] = Bs[k][tcol * 5 + j];
#pragma unroll
            for (int i = 0; i < 4; i++)
#pragma unroll
                for (int j = 0; j < 5; j++) acc[i][j] += a[i] * b[j];
        }
        __syncthreads();
    }

#pragma unroll
    for (int i = 0; i < 4; i++) {
        int gr = rowBase + trow * 4 + i;
        if (gr >= M) continue;
#pragma unroll
        for (int j = 0; j < 5; j++) C[(size_t)gr * 40 + tcol * 5 + j] = acc[i][j];
    }
}

// ---------------- aggregate (D=128): warp per node, self+bias fused ----------------
__global__ void aggregate128_kernel(const float* __restrict__ H, float* __restrict__ C,
                                    const float* __restrict__ bias) {
    int warp = (blockIdx.x * blockDim.x + threadIdx.x) >> 5;
    int lane = threadIdx.x & 31;
    if (warp >= NN) return;
    int start = g_rowstart[warp];
    int end   = start + g_cnt[warp];
    const float4* H4 = (const float4*)H;
    float4 acc = make_float4(0.f, 0.f, 0.f, 0.f);
    int j = start;
    for (; j + 1 < end; j += 2) {
        int   s0 = g_esrc[j],  s1 = g_esrc[j + 1];
        float w0 = g_ew[j],    w1 = g_ew[j + 1];
        float4 h0 = H4[(size_t)s0 * 32 + lane];
        float4 h1 = H4[(size_t)s1 * 32 + lane];
        acc.x += h0.x * w0; acc.y += h0.y * w0; acc.z += h0.z * w0; acc.w += h0.w * w0;
        acc.x += h1.x * w1; acc.y += h1.y * w1; acc.z += h1.z * w1; acc.w += h1.w * w1;
    }
    if (j < end) {
        int s = g_esrc[j]; float w = g_ew[j];
        float4 h = H4[(size_t)s * 32 + lane];
        acc.x += h.x * w; acc.y += h.y * w; acc.z += h.z * w; acc.w += h.w * w;
    }
    float di = g_dinv[warp];
    float dii = di * di;
    float4 hs = H4[(size_t)warp * 32 + lane];
    float4 b4 = ((const float4*)bias)[lane];
    ((float4*)C)[(size_t)warp * 32 + lane] =
        make_float4(acc.x + hs.x * dii + b4.x, acc.y + hs.y * dii + b4.y,
                    acc.z + hs.z * dii + b4.z, acc.w + hs.w * dii + b4.w);
}

// ---------------- BN column stats + prep ----------------
__global__ void colstats_kernel(const float* __restrict__ C) {
    int f  = threadIdx.x;
    int r0 = blockIdx.x * 256;
    int r1 = r0 + 256;
    if (r1 > NN) r1 = NN;
    float s = 0.0f, s2 = 0.0f;
    for (int r = r0; r < r1; r++) {
        float v = C[(size_t)r * DH + f];
        s += v;
        s2 += v * v;
    }
    atomicAdd(&g_colsum[f], s);
    atomicAdd(&g_colsq[f], s2);
}

__global__ void bn_prep_kernel(const float* __restrict__ g, const float* __restrict__ be) {
    int f = threadIdx.x;
    if (f >= DH) return;
    float mu  = g_colsum[f] / (float)NN;
    float var = g_colsq[f] / (float)NN - mu * mu;
    float sc  = g[f] * rsqrtf(var + BN_EPS);
    g_scale[f] = sc;
    g_shift[f] = be[f] - mu * sc;
    g_colsum[f] = 0.0f;
    g_colsq[f]  = 0.0f;
}

// ---------------- layer-3: aggregate (D=40) + self + bias + log-softmax ----------------
__global__ void aggregate40_softmax_kernel(const float* __restrict__ H,
                                           const float* __restrict__ bf,
                                           float* __restrict__ out) {
    int warp = (blockIdx.x * blockDim.x + threadIdx.x) >> 5;
    int lane = threadIdx.x & 31;
    if (warp >= NN) return;
    int start = g_rowstart[warp];
    int end   = start + g_cnt[warp];
    if (lane == 0) { g_cnt[warp] = 0; g_fill[warp] = 0; }   // reset for next run
    const float4* H4 = (const float4*)H;
    bool act = lane < 10;

    float4 acc = make_float4(0.f, 0.f, 0.f, 0.f);
    for (int j = start; j < end; j++) {
        int s = g_esrc[j]; float ww = g_ew[j];
        if (act) {
            float4 h = H4[(size_t)s * 10 + lane];
            acc.x += h.x * ww; acc.y += h.y * ww; acc.z += h.z * ww; acc.w += h.w * ww;
        }
    }
    float4 v = make_float4(-1e30f, -1e30f, -1e30f, -1e30f);
    if (act) {
        float di = g_dinv[warp];
        float dii = di * di;
        float4 hs = H4[(size_t)warp * 10 + lane];
        float4 b4 = ((const float4*)bf)[lane];
        v = make_float4(acc.x + hs.x * dii + b4.x, acc.y + hs.y * dii + b4.y,
                        acc.z + hs.z * dii + b4.z, acc.w + hs.w * dii + b4.w);
    }

    float m = fmaxf(fmaxf(v.x, v.y), fmaxf(v.z, v.w));
#pragma unroll
    for (int o = 16; o > 0; o >>= 1) m = fmaxf(m, __shfl_xor_sync(0xffffffffu, m, o));

    float s = 0.0f;
    if (act) s = expf(v.x - m) + expf(v.y - m) + expf(v.z - m) + expf(v.w - m);
#pragma unroll
    for (int o = 16; o > 0; o >>= 1) s += __shfl_xor_sync(0xffffffffu, s, o);

    float ls = m + logf(s);
    if (act) {
        ((float4*)out)[(size_t)warp * 10 + lane] =
            make_float4(v.x - ls, v.y - ls, v.z - ls, v.w - ls);
    }
}

// ---------------- host launch ----------------
extern "C" void kernel_launch(void* const* d_in, const int* in_sizes, int n_in,
                              void* d_out, int out_size) {
    const float* x   = (const float*)d_in[0];
    const int*   ei  = (const int*)d_in[1];    // int32 edge_index
    const float* W1  = (const float*)d_in[2];
    const float* b1  = (const float*)d_in[3];
    const float* g1  = (const float*)d_in[4];
    const float* be1 = (const float*)d_in[5];
    const float* W2  = (const float*)d_in[6];
    const float* b2  = (const float*)d_in[7];
    const float* g2  = (const float*)d_in[8];
    const float* be2 = (const float*)d_in[9];
    const float* Wf  = (const float*)d_in[10];
    const float* bf  = (const float*)d_in[11];
    float* out = (float*)d_out;

    float *bufB, *bufC;
    uint32_t *w1t, *w2t;
    cudaGetSymbolAddress((void**)&bufB, g_bufB);
    cudaGetSymbolAddress((void**)&bufC, g_bufC);
    cudaGetSymbolAddress((void**)&w1t, g_W1t);
    cudaGetSymbolAddress((void**)&w2t, g_W2t);

    cudaFuncSetAttribute(gemm_mma_kernel<false>, cudaFuncAttributeMaxDynamicSharedMemorySize, SMEM_GEMM_BYTES);
    cudaFuncSetAttribute(gemm_mma_kernel<true>,  cudaFuncAttributeMaxDynamicSharedMemorySize, SMEM_GEMM_BYTES);

    const int T = 256;
    const int nBlocksN = (NN + T - 1) / T;
    const int nBlocksE = (EE + T - 1) / T;
    const int gemmBlocks = (NN + 127) / 128;        // 782
    const int warpBlocks = (NN * 32 + T - 1) / T;
    const int statBlocks = (NN + 255) / 256;

    // --- prep + CSR build ---
    prep_w_kernel<<<128, 256>>>(W1, W2);
    count_kernel<<<nBlocksE, T>>>(ei);
    scan_block_kernel<<<NBLK, SB>>>();
    scan_bsum_kernel<<<1, 256>>>();
    scan_finalize_kernel<<<nBlocksN, T>>>();
    fill_kernel<<<nBlocksE, T>>>(ei);

    // ---------------- layer 1 ----------------
    gemm_mma_kernel<false><<<gemmBlocks, T, SMEM_GEMM_BYTES>>>(x, w1t, bufB, NN);
    aggregate128_kernel<<<warpBlocks, T>>>(bufB, bufC, b1);
    colstats_kernel<<<statBlocks, 128>>>(bufC);
    bn_prep_kernel<<<1, 128>>>(g1, be1);

    // ---------------- layer 2 (BN+ReLU fused into A-load) ----------------
    gemm_mma_kernel<true><<<gemmBlocks, T, SMEM_GEMM_BYTES>>>(bufC, w2t, bufB, NN);
    aggregate128_kernel<<<warpBlocks, T>>>(bufB, bufC, b2);
    colstats_kernel<<<statBlocks, 128>>>(bufC);
    bn_prep_kernel<<<1, 128>>>(g2, be2);

    // ---------------- layer 3 ----------------
    gemm40_kernel<<<dim3(1, gemmBlocks), T>>>(bufC, Wf, bufB, NN);
    aggregate40_softmax_kernel<<<warpBlocks, T>>>(bufB, bf, out);
}

// round 14
// speedup vs baseline: 1.4645x; 1.0423x over previous
#include <cuda_runtime.h>
#include <cuda_fp16.h>
#include <math.h>
#include <stdint.h>

#define NN 100000
#define EE 1600000
#define DH 128
#define DOUT 40
#define BN_EPS 1e-5f
#define SB 512
#define NBLK ((NN + SB - 1) / SB)   // 196

// mma GEMM smem strides (in floats). AST%32==4 and BST%32==8 keep the
// m16n8k8 A/B fragment LDS patterns bank-conflict-free.
#define AST 132
#define BST 136
#define SMEM_GEMM_BYTES ((128 * AST + 128 * BST) * 4)   // 137216

// ---------------- scratch (device globals) ----------------
__device__ __half   g_bufH[(size_t)NN * DH];   // gemm output h (fp16 messages)
__device__ float    g_bufC[(size_t)NN * DH];   // aggregated output (fp32)
__device__ uint32_t g_W1t[128 * BST];          // W as tf32, [k][n] stride BST
__device__ uint32_t g_W2t[128 * BST];
__device__ float    g_dinv[NN];
__device__ int      g_cnt[NN];
__device__ int      g_fill[NN];
__device__ int      g_rowstart[NN];
__device__ int      g_incl[NN];
__device__ int      g_bsum[NBLK];
__device__ int      g_boff[NBLK];
__device__ int      g_esrc[EE];
__device__ float    g_ew[EE];
__device__ float    g_colsum[DH];
__device__ float    g_colsq[DH];
__device__ float    g_scale[DH];
__device__ float    g_shift[DH];

__device__ __forceinline__ uint32_t cvt_tf32(float f) {
    uint32_t u;
    asm("cvt.rna.tf32.f32 %0, %1;" : "=r"(u) : "f"(f));
    return u;
}

__device__ __forceinline__ void mma_tf32(float* d, const uint32_t* a, uint32_t b0, uint32_t b1) {
    asm volatile(
        "mma.sync.aligned.m16n8k8.row.col.f32.tf32.tf32.f32 "
        "{%0,%1,%2,%3}, {%4,%5,%6,%7}, {%8,%9}, {%0,%1,%2,%3};"
        : "+f"(d[0]), "+f"(d[1]), "+f"(d[2]), "+f"(d[3])
        : "r"(a[0]), "r"(a[1]), "r"(a[2]), "r"(a[3]), "r"(b0), "r"(b1));
}

// unpack 4 halves (uint2) -> 2 float2, fma into float4 acc
__device__ __forceinline__ void fma_h4(float4& acc, uint2 u, float w) {
    __half2* ph = (__half2*)&u;
    float2 f0 = __half22float2(ph[0]);
    float2 f1 = __half22float2(ph[1]);
    acc.x += f0.x * w; acc.y += f0.y * w;
    acc.z += f1.x * w; acc.w += f1.y * w;
}

// ---------------- W precompute: tf32 convert, [k][n] stride BST ----------------
__global__ void prep_w_kernel(const float* __restrict__ W1, const float* __restrict__ W2) {
    int idx = blockIdx.x * blockDim.x + threadIdx.x;
    if (idx >= 32768) return;
    int which = idx >> 14;
    int rem = idx & 16383;
    int k = rem >> 7;
    int n = rem & 127;
    const float* W = which ? W2 : W1;
    uint32_t* dst = which ? g_W2t : g_W1t;
    dst[k * BST + n] = cvt_tf32(W[k * 128 + n]);
}

// ---------------- CSR build (edge_index is int32) ----------------
__global__ void count_kernel(const int* __restrict__ ei) {
    int e = blockIdx.x * blockDim.x + threadIdx.x;
    if (e >= EE) return;
    int d = ei[EE + e];
    if ((unsigned)d < NN) atomicAdd(&g_cnt[d], 1);
}

__global__ void scan_block_kernel() {
    __shared__ int sm[SB];
    int i = blockIdx.x * SB + threadIdx.x;
    int v = (i < NN) ? g_cnt[i] : 0;
    if (i < NN) g_dinv[i] = rsqrtf((float)v + 1.0f);
    sm[threadIdx.x] = v;
    __syncthreads();
#pragma unroll
    for (int off = 1; off < SB; off <<= 1) {
        int t = (threadIdx.x >= off) ? sm[threadIdx.x - off] : 0;
        __syncthreads();
        sm[threadIdx.x] += t;
        __syncthreads();
    }
    if (i < NN) g_incl[i] = sm[threadIdx.x];
    if (threadIdx.x == SB - 1) g_bsum[blockIdx.x] = sm[SB - 1];
}

__global__ void scan_bsum_kernel() {
    __shared__ int sm[256];
    int v = (threadIdx.x < NBLK) ? g_bsum[threadIdx.x] : 0;
    sm[threadIdx.x] = v;
    __syncthreads();
#pragma unroll
    for (int off = 1; off < 256; off <<= 1) {
        int t = (threadIdx.x >= off) ? sm[threadIdx.x - off] : 0;
        __syncthreads();
        sm[threadIdx.x] += t;
        __syncthreads();
    }
    if (threadIdx.x < NBLK) g_boff[threadIdx.x] = sm[threadIdx.x] - v;
}

__global__ void scan_finalize_kernel() {
    int i = blockIdx.x * blockDim.x + threadIdx.x;
    if (i >= NN) return;
    g_rowstart[i] = g_incl[i] + g_boff[i / SB] - g_cnt[i];
}

__global__ void fill_kernel(const int* __restrict__ ei) {
    int e = blockIdx.x * blockDim.x + threadIdx.x;
    if (e >= EE) return;
    int s = ei[e];
    int d = ei[EE + e];
    if ((unsigned)s >= NN || (unsigned)d >= NN) return;
    int pos = g_rowstart[d] + atomicAdd(&g_fill[d], 1);
    g_esrc[pos] = s;
    g_ew[pos] = g_dinv[s] * g_dinv[d];
}

// ---------------- TF32 mma.sync GEMM: H[M,128] = act(A)[M,128] @ W, fp16 out ----------------
// 256 threads = 8 warps (4 on M x 2 on N); warp computes 32x64 via m16n8k8.
template<bool FUSE>
__global__ void __launch_bounds__(256, 1)
gemm_mma_kernel(const float* __restrict__ A, const uint32_t* __restrict__ Wt,
                __half* __restrict__ H, int M) {
    extern __shared__ uint32_t smu[];
    uint32_t* sA = smu;                  // [128][AST]
    uint32_t* sBm = smu + 128 * AST;     // [128][BST]

    int t = threadIdx.x;
    int lane = t & 31;
    int wid = t >> 5;
    int warpM = wid & 3;
    int warpN = wid >> 2;
    int rowBase = blockIdx.x * 128;

    // ---- B tile: linear copy of pre-converted W ----
    {
        const uint4* g = (const uint4*)Wt;
        uint4* d = (uint4*)sBm;
        for (int i = t; i < (128 * BST) / 4; i += 256) d[i] = g[i];
    }

    // ---- A tile: row-major load, tf32 convert (+BN/ReLU fuse) ----
    {
        int row = t >> 1;
        int half = t & 1;
        int gr = rowBase + row;
        const float4* Ar = (const float4*)(A + (size_t)gr * 128 + half * 64);
        uint32_t* dst = sA + row * AST + half * 64;
#pragma unroll
        for (int i = 0; i < 16; i++) {
            float4 v = (gr < M) ? Ar[i] : make_float4(0.f, 0.f, 0.f, 0.f);
            if (FUSE) {
                int col = half * 64 + i * 4;
                v.x = fmaxf(v.x * g_scale[col + 0] + g_shift[col + 0], 0.0f);
                v.y = fmaxf(v.y * g_scale[col + 1] + g_shift[col + 1], 0.0f);
                v.z = fmaxf(v.z * g_scale[col + 2] + g_shift[col + 2], 0.0f);
                v.w = fmaxf(v.w * g_scale[col + 3] + g_shift[col + 3], 0.0f);
            }
            *(uint4*)(dst + i * 4) =
                make_uint4(cvt_tf32(v.x), cvt_tf32(v.y), cvt_tf32(v.z), cvt_tf32(v.w));
        }
    }
    __syncthreads();

    float acc[2][8][4];
#pragma unroll
    for (int mi = 0; mi < 2; mi++)
#pragma unroll
        for (int nj = 0; nj < 8; nj++)
#pragma unroll
            for (int q = 0; q < 4; q++) acc[mi][nj][q] = 0.0f;

    int ar = warpM * 32 + (lane >> 2);
    int ac = lane & 3;
    int bn = warpN * 64 + (lane >> 2);
    int bk = lane & 3;

#pragma unroll 4
    for (int k0 = 0; k0 < 128; k0 += 8) {
        uint32_t a[2][4];
#pragma unroll
        for (int mi = 0; mi < 2; mi++) {
            const uint32_t* p = sA + (ar + mi * 16) * AST + k0 + ac;
            a[mi][0] = p[0];
            a[mi][1] = p[8 * AST];
            a[mi][2] = p[4];
            a[mi][3] = p[8 * AST + 4];
        }
#pragma unroll
        for (int nj = 0; nj < 8; nj++) {
            const uint32_t* q = sBm + (k0 + bk) * BST + bn + nj * 8;
            uint32_t b0 = q[0];
            uint32_t b1 = q[4 * BST];
            mma_tf32(acc[0][nj], a[0], b0, b1);
            mma_tf32(acc[1][nj], a[1], b0, b1);
        }
    }

    // ---- store H as fp16 (half2 per thread-fragment-pair) ----
#pragma unroll
    for (int mi = 0; mi < 2; mi++) {
        int r0 = rowBase + warpM * 32 + mi * 16 + (lane >> 2);
        int r1 = r0 + 8;
#pragma unroll
        for (int nj = 0; nj < 8; nj++) {
            int col = warpN * 64 + nj * 8 + 2 * (lane & 3);
            if (r0 < M)
                *(__half2*)&H[(size_t)r0 * 128 + col] = __floats2half2_rn(acc[mi][nj][0], acc[mi][nj][1]);
            if (r1 < M)
                *(__half2*)&H[(size_t)r1 * 128 + col] = __floats2half2_rn(acc[mi][nj][2], acc[mi][nj][3]);
        }
    }
}

// ---------------- GEMM 128x40 fp32 compute, fp16 out, fused BN+ReLU on A ----------------
__global__ void __launch_bounds__(256, 4)
gemm40_kernel(const float* __restrict__ A, const float* __restrict__ W,
              __half* __restrict__ H, int M) {
    __shared__ float As[16][128];
    __shared__ float Bs[16][40];

    int t = threadIdx.x;
    int trow = t >> 3;
    int tcol = t & 7;
    int rowBase = blockIdx.y * 128;

    int arow = t >> 1;
    int acol = (t & 1) * 8;

    float acc[4][5];
#pragma unroll
    for (int i = 0; i < 4; i++)
#pragma unroll
        for (int j = 0; j < 5; j++) acc[i][j] = 0.0f;

    for (int k0 = 0; k0 < 128; k0 += 16) {
        int gr = rowBase + arow;
        float av[8];
        if (gr < M) {
            float4 a0 = *(const float4*)&A[(size_t)gr * 128 + k0 + acol];
            float4 a1 = *(const float4*)&A[(size_t)gr * 128 + k0 + acol + 4];
            av[0] = a0.x; av[1] = a0.y; av[2] = a0.z; av[3] = a0.w;
            av[4] = a1.x; av[5] = a1.y; av[6] = a1.z; av[7] = a1.w;
        } else {
#pragma unroll
            for (int i = 0; i < 8; i++) av[i] = 0.0f;
        }
#pragma unroll
        for (int i = 0; i < 8; i++) {
            int col = k0 + acol + i;
            av[i] = fmaxf(av[i] * g_scale[col] + g_shift[col], 0.0f);
            As[acol + i][arow] = av[i];
        }
        if (t < 160) {
            int brow = t / 10;
            int bcol = (t % 10) * 4;
            *(float4*)&Bs[brow][bcol] = *(const float4*)&W[(size_t)(k0 + brow) * 40 + bcol];
        }
        __syncthreads();

#pragma unroll
        for (int k = 0; k < 16; k++) {
            float a[4], b[5];
            *(float4*)&a[0] = *(const float4*)&As[k][trow * 4];
#pragma unroll
            for (int j = 0; j < 5; j++) b[j] = Bs[k][tcol * 5 + j];
#pragma unroll
            for (int i = 0; i < 4; i++)
#pragma unroll
                for (int j = 0; j < 5; j++) acc[i][j] += a[i] * b[j];
        }
        __syncthreads();
    }

#pragma unroll
    for (int i = 0; i < 4; i++) {
        int gr = rowBase + trow * 4 + i;
        if (gr >= M) continue;
#pragma unroll
        for (int j = 0; j < 5; j++)
            H[(size_t)gr * 40 + tcol * 5 + j] = __float2half_rn(acc[i][j]);
    }
}

// ---------------- aggregate (D=128): warp per node, fp16 gather, self+bias fused ----------------
__global__ void aggregate128_kernel(const __half* __restrict__ H, float* __restrict__ C,
                                    const float* __restrict__ bias) {
    int warp = (blockIdx.x * blockDim.x + threadIdx.x) >> 5;
    int lane = threadIdx.x & 31;
    if (warp >= NN) return;
    int start = g_rowstart[warp];
    int end   = start + g_cnt[warp];
    const uint2* H2 = (const uint2*)H;   // 4 halves per lane per node
    float4 acc = make_float4(0.f, 0.f, 0.f, 0.f);
    int j = start;
    for (; j + 1 < end; j += 2) {
        int   s0 = g_esrc[j],  s1 = g_esrc[j + 1];
        float w0 = g_ew[j],    w1 = g_ew[j + 1];
        uint2 u0 = H2[(size_t)s0 * 32 + lane];
        uint2 u1 = H2[(size_t)s1 * 32 + lane];
        fma_h4(acc, u0, w0);
        fma_h4(acc, u1, w1);
    }
    if (j < end) {
        int s = g_esrc[j];
        fma_h4(acc, H2[(size_t)s * 32 + lane], g_ew[j]);
    }
    float di = g_dinv[warp];
    fma_h4(acc, H2[(size_t)warp * 32 + lane], di * di);
    float4 b4 = ((const float4*)bias)[lane];
    ((float4*)C)[(size_t)warp * 32 + lane] =
        make_float4(acc.x + b4.x, acc.y + b4.y, acc.z + b4.z, acc.w + b4.w);
}

// ---------------- BN column stats + prep ----------------
__global__ void colstats_kernel(const float* __restrict__ C) {
    int f  = threadIdx.x;
    int r0 = blockIdx.x * 256;
    int r1 = r0 + 256;
    if (r1 > NN) r1 = NN;
    float s = 0.0f, s2 = 0.0f;
    for (int r = r0; r < r1; r++) {
        float v = C[(size_t)r * DH + f];
        s += v;
        s2 += v * v;
    }
    atomicAdd(&g_colsum[f], s);
    atomicAdd(&g_colsq[f], s2);
}

__global__ void bn_prep_kernel(const float* __restrict__ g, const float* __restrict__ be) {
    int f = threadIdx.x;
    if (f >= DH) return;
    float mu  = g_colsum[f] / (float)NN;
    float var = g_colsq[f] / (float)NN - mu * mu;
    float sc  = g[f] * rsqrtf(var + BN_EPS);
    g_scale[f] = sc;
    g_shift[f] = be[f] - mu * sc;
    g_colsum[f] = 0.0f;
    g_colsq[f]  = 0.0f;
}

// ---------------- layer-3: fp16 aggregate (D=40) + self + bias + log-softmax ----------------
__global__ void aggregate40_softmax_kernel(const __half* __restrict__ H,
                                           const float* __restrict__ bf,
                                           float* __restrict__ out) {
    int warp = (blockIdx.x * blockDim.x + threadIdx.x) >> 5;
    int lane = threadIdx.x & 31;
    if (warp >= NN) return;
    int start = g_rowstart[warp];
    int end   = start + g_cnt[warp];
    if (lane == 0) { g_cnt[warp] = 0; g_fill[warp] = 0; }   // reset for next run
    const uint2* H2 = (const uint2*)H;   // 40 halves = 10 uint2 per node
    bool act = lane < 10;

    float4 acc = make_float4(0.f, 0.f, 0.f, 0.f);
    for (int j = start; j < end; j++) {
        int s = g_esrc[j]; float ww = g_ew[j];
        if (act) fma_h4(acc, H2[(size_t)s * 10 + lane], ww);
    }
    float4 v = make_float4(-1e30f, -1e30f, -1e30f, -1e30f);
    if (act) {
        float di = g_dinv[warp];
        fma_h4(acc, H2[(size_t)warp * 10 + lane], di * di);
        float4 b4 = ((const float4*)bf)[lane];
        v = make_float4(acc.x + b4.x, acc.y + b4.y, acc.z + b4.z, acc.w + b4.w);
    }

    float m = fmaxf(fmaxf(v.x, v.y), fmaxf(v.z, v.w));
#pragma unroll
    for (int o = 16; o > 0; o >>= 1) m = fmaxf(m, __shfl_xor_sync(0xffffffffu, m, o));

    float s = 0.0f;
    if (act) s = expf(v.x - m) + expf(v.y - m) + expf(v.z - m) + expf(v.w - m);
#pragma unroll
    for (int o = 16; o > 0; o >>= 1) s += __shfl_xor_sync(0xffffffffu, s, o);

    float ls = m + logf(s);
    if (act) {
        ((float4*)out)[(size_t)warp * 10 + lane] =
            make_float4(v.x - ls, v.y - ls, v.z - ls, v.w - ls);
    }
}

// ---------------- host launch ----------------
extern "C" void kernel_launch(void* const* d_in, const int* in_sizes, int n_in,
                              void* d_out, int out_size) {
    const float* x   = (const float*)d_in[0];
    const int*   ei  = (const int*)d_in[1];    // int32 edge_index
    const float* W1  = (const float*)d_in[2];
    const float* b1  = (const float*)d_in[3];
    const float* g1  = (const float*)d_in[4];
    const float* be1 = (const float*)d_in[5];
    const float* W2  = (const float*)d_in[6];
    const float* b2  = (const float*)d_in[7];
    const float* g2  = (const float*)d_in[8];
    const float* be2 = (const float*)d_in[9];
    const float* Wf  = (const float*)d_in[10];
    const float* bf  = (const float*)d_in[11];
    float* out = (float*)d_out;

    __half* bufH;
    float* bufC;
    uint32_t *w1t, *w2t;
    cudaGetSymbolAddress((void**)&bufH, g_bufH);
    cudaGetSymbolAddress((void**)&bufC, g_bufC);
    cudaGetSymbolAddress((void**)&w1t, g_W1t);
    cudaGetSymbolAddress((void**)&w2t, g_W2t);

    cudaFuncSetAttribute(gemm_mma_kernel<false>, cudaFuncAttributeMaxDynamicSharedMemorySize, SMEM_GEMM_BYTES);
    cudaFuncSetAttribute(gemm_mma_kernel<true>,  cudaFuncAttributeMaxDynamicSharedMemorySize, SMEM_GEMM_BYTES);

    const int T = 256;
    const int nBlocksN = (NN + T - 1) / T;
    const int nBlocksE = (EE + T - 1) / T;
    const int gemmBlocks = (NN + 127) / 128;
    const int warpBlocks = (NN * 32 + T - 1) / T;
    const int statBlocks = (NN + 255) / 256;

    // --- prep + CSR build ---
    prep_w_kernel<<<128, 256>>>(W1, W2);
    count_kernel<<<nBlocksE, T>>>(ei);
    scan_block_kernel<<<NBLK, SB>>>();
    scan_bsum_kernel<<<1, 256>>>();
    scan_finalize_kernel<<<nBlocksN, T>>>();
    fill_kernel<<<nBlocksE, T>>>(ei);

    // ---------------- layer 1 ----------------
    gemm_mma_kernel<false><<<gemmBlocks, T, SMEM_GEMM_BYTES>>>(x, w1t, bufH, NN);
    aggregate128_kernel<<<warpBlocks, T>>>(bufH, bufC, b1);
    colstats_kernel<<<statBlocks, 128>>>(bufC);
    bn_prep_kernel<<<1, 128>>>(g1, be1);

    // ---------------- layer 2 (BN+ReLU fused into A-load) ----------------
    gemm_mma_kernel<true><<<gemmBlocks, T, SMEM_GEMM_BYTES>>>(bufC, w2t, bufH, NN);
    aggregate128_kernel<<<warpBlocks, T>>>(bufH, bufC, b2);
    colstats_kernel<<<statBlocks, 128>>>(bufC);
    bn_prep_kernel<<<1, 128>>>(g2, be2);

    // ---------------- layer 3 ----------------
    gemm40_kernel<<<dim3(1, gemmBlocks), T>>>(bufC, Wf, bufH, NN);
    aggregate40_softmax_kernel<<<warpBlocks, T>>>(bufH, bf, out);
}

// round 15
// speedup vs baseline: 1.5617x; 1.0664x over previous
#include <cuda_runtime.h>
#include <cuda_fp16.h>
#include <math.h>
#include <stdint.h>

#define NN 100000
#define EE 1600000
#define DH 128
#define DOUT 40
#define BN_EPS 1e-5f
#define SB 512
#define NBLK ((NN + SB - 1) / SB)   // 196

// mma GEMM smem strides (in floats). AST%32==4 and BST%32==8 keep the
// m16n8k8 A/B fragment LDS patterns bank-conflict-free.
#define AST 132
#define BST 136
#define SMEM_GEMM_BYTES ((128 * AST + 128 * BST) * 4)   // 137216

// ---------------- scratch (device globals) ----------------
__device__ __half   g_bufH[(size_t)NN * DH];   // gemm output h (fp16 messages)
__device__ float    g_bufC[(size_t)NN * DH];   // aggregated output (fp32)
__device__ float    g_dinv[NN];
__device__ int      g_cnt[NN];
__device__ int      g_fill[NN];
__device__ int      g_rowstart[NN];
__device__ int      g_incl[NN];
__device__ int      g_bsum[NBLK];
__device__ int      g_boff[NBLK];
__device__ int2     g_edge[EE];                // CSR: (src, edge-norm-as-int) by dst
__device__ float    g_colsum[DH];
__device__ float    g_colsq[DH];
__device__ float    g_scale[DH];
__device__ float    g_shift[DH];

__device__ __forceinline__ uint32_t cvt_tf32(float f) {
    uint32_t u;
    asm("cvt.rna.tf32.f32 %0, %1;" : "=r"(u) : "f"(f));
    return u;
}

__device__ __forceinline__ void mma_tf32(float* d, const uint32_t* a, uint32_t b0, uint32_t b1) {
    asm volatile(
        "mma.sync.aligned.m16n8k8.row.col.f32.tf32.tf32.f32 "
        "{%0,%1,%2,%3}, {%4,%5,%6,%7}, {%8,%9}, {%0,%1,%2,%3};"
        : "+f"(d[0]), "+f"(d[1]), "+f"(d[2]), "+f"(d[3])
        : "r"(a[0]), "r"(a[1]), "r"(a[2]), "r"(a[3]), "r"(b0), "r"(b1));
}

// unpack 4 halves (uint2) -> 2 float2, fma into float4 acc
__device__ __forceinline__ void fma_h4(float4& acc, uint2 u, float w) {
    __half2* ph = (__half2*)&u;
    float2 f0 = __half22float2(ph[0]);
    float2 f1 = __half22float2(ph[1]);
    acc.x += f0.x * w; acc.y += f0.y * w;
    acc.z += f1.x * w; acc.w += f1.y * w;
}

// ---------------- CSR build (edge_index is int32) ----------------
__global__ void count_kernel(const int* __restrict__ ei) {
    int e = blockIdx.x * blockDim.x + threadIdx.x;
    if (e >= EE) return;
    int d = ei[EE + e];
    if ((unsigned)d < NN) atomicAdd(&g_cnt[d], 1);
}

__global__ void scan_block_kernel() {
    __shared__ int sm[SB];
    int i = blockIdx.x * SB + threadIdx.x;
    int v = (i < NN) ? g_cnt[i] : 0;
    if (i < NN) g_dinv[i] = rsqrtf((float)v + 1.0f);
    sm[threadIdx.x] = v;
    __syncthreads();
#pragma unroll
    for (int off = 1; off < SB; off <<= 1) {
        int t = (threadIdx.x >= off) ? sm[threadIdx.x - off] : 0;
        __syncthreads();
        sm[threadIdx.x] += t;
        __syncthreads();
    }
    if (i < NN) g_incl[i] = sm[threadIdx.x];
    if (threadIdx.x == SB - 1) g_bsum[blockIdx.x] = sm[SB - 1];
}

__global__ void scan_bsum_kernel() {
    __shared__ int sm[256];
    int v = (threadIdx.x < NBLK) ? g_bsum[threadIdx.x] : 0;
    sm[threadIdx.x] = v;
    __syncthreads();
#pragma unroll
    for (int off = 1; off < 256; off <<= 1) {
        int t = (threadIdx.x >= off) ? sm[threadIdx.x - off] : 0;
        __syncthreads();
        sm[threadIdx.x] += t;
        __syncthreads();
    }
    if (threadIdx.x < NBLK) g_boff[threadIdx.x] = sm[threadIdx.x] - v;
}

__global__ void scan_finalize_kernel() {
    int i = blockIdx.x * blockDim.x + threadIdx.x;
    if (i >= NN) return;
    g_rowstart[i] = g_incl[i] + g_boff[i / SB] - g_cnt[i];
}

__global__ void fill_kernel(const int* __restrict__ ei) {
    int e = blockIdx.x * blockDim.x + threadIdx.x;
    if (e >= EE) return;
    int s = ei[e];
    int d = ei[EE + e];
    if ((unsigned)s >= NN || (unsigned)d >= NN) return;
    int pos = g_rowstart[d] + atomicAdd(&g_fill[d], 1);
    g_edge[pos] = make_int2(s, __float_as_int(g_dinv[s] * g_dinv[d]));
}

// ---------------- TF32 mma.sync GEMM: H[M,128] = act(A)[M,128] @ W, fp16 out ----------------
// 256 threads = 8 warps (4 on M x 2 on N); warp computes 32x64 via m16n8k8.
// W is raw fp32 [128][128]; converted to tf32 during the smem B-tile fill.
template<bool FUSE>
__global__ void __launch_bounds__(256, 1)
gemm_mma_kernel(const float* __restrict__ A, const float* __restrict__ W,
                __half* __restrict__ H, int M) {
    extern __shared__ uint32_t smu[];
    uint32_t* sA = smu;                  // [128][AST]
    uint32_t* sBm = smu + 128 * AST;     // [128][BST]

    int t = threadIdx.x;
    int lane = t & 31;
    int wid = t >> 5;
    int warpM = wid & 3;
    int warpN = wid >> 2;
    int rowBase = blockIdx.x * 128;

    int row = t >> 1;
    int half = t & 1;

    // ---- B tile: fp32 W -> tf32 smem [k][n] stride BST ----
    {
        const float4* Wr = (const float4*)(W + (size_t)row * 128 + half * 64);
        uint32_t* dst = sBm + row * BST + half * 64;
#pragma unroll
        for (int i = 0; i < 16; i++) {
            float4 v = Wr[i];
            *(uint4*)(dst + i * 4) =
                make_uint4(cvt_tf32(v.x), cvt_tf32(v.y), cvt_tf32(v.z), cvt_tf32(v.w));
        }
    }

    // ---- A tile: row-major load, tf32 convert (+BN/ReLU fuse) ----
    {
        int gr = rowBase + row;
        const float4* Ar = (const float4*)(A + (size_t)gr * 128 + half * 64);
        uint32_t* dst = sA + row * AST + half * 64;
#pragma unroll
        for (int i = 0; i < 16; i++) {
            float4 v = (gr < M) ? Ar[i] : make_float4(0.f, 0.f, 0.f, 0.f);
            if (FUSE) {
                int col = half * 64 + i * 4;
                v.x = fmaxf(v.x * g_scale[col + 0] + g_shift[col + 0], 0.0f);
                v.y = fmaxf(v.y * g_scale[col + 1] + g_shift[col + 1], 0.0f);
                v.z = fmaxf(v.z * g_scale[col + 2] + g_shift[col + 2], 0.0f);
                v.w = fmaxf(v.w * g_scale[col + 3] + g_shift[col + 3], 0.0f);
            }
            *(uint4*)(dst + i * 4) =
                make_uint4(cvt_tf32(v.x), cvt_tf32(v.y), cvt_tf32(v.z), cvt_tf32(v.w));
        }
    }
    __syncthreads();

    float acc[2][8][4];
#pragma unroll
    for (int mi = 0; mi < 2; mi++)
#pragma unroll
        for (int nj = 0; nj < 8; nj++)
#pragma unroll
            for (int q = 0; q < 4; q++) acc[mi][nj][q] = 0.0f;

    int ar = warpM * 32 + (lane >> 2);
    int ac = lane & 3;
    int bn = warpN * 64 + (lane >> 2);
    int bk = lane & 3;

#pragma unroll 4
    for (int k0 = 0; k0 < 128; k0 += 8) {
        uint32_t a[2][4];
#pragma unroll
        for (int mi = 0; mi < 2; mi++) {
            const uint32_t* p = sA + (ar + mi * 16) * AST + k0 + ac;
            a[mi][0] = p[0];
            a[mi][1] = p[8 * AST];
            a[mi][2] = p[4];
            a[mi][3] = p[8 * AST + 4];
        }
#pragma unroll
        for (int nj = 0; nj < 8; nj++) {
            const uint32_t* q = sBm + (k0 + bk) * BST + bn + nj * 8;
            uint32_t b0 = q[0];
            uint32_t b1 = q[4 * BST];
            mma_tf32(acc[0][nj], a[0], b0, b1);
            mma_tf32(acc[1][nj], a[1], b0, b1);
        }
    }

    // ---- store H as fp16 ----
#pragma unroll
    for (int mi = 0; mi < 2; mi++) {
        int r0 = rowBase + warpM * 32 + mi * 16 + (lane >> 2);
        int r1 = r0 + 8;
#pragma unroll
        for (int nj = 0; nj < 8; nj++) {
            int col = warpN * 64 + nj * 8 + 2 * (lane & 3);
            if (r0 < M)
                *(__half2*)&H[(size_t)r0 * 128 + col] = __floats2half2_rn(acc[mi][nj][0], acc[mi][nj][1]);
            if (r1 < M)
                *(__half2*)&H[(size_t)r1 * 128 + col] = __floats2half2_rn(acc[mi][nj][2], acc[mi][nj][3]);
        }
    }
}

// ---------------- GEMM 128x40 fp32 compute, fp16 out, fused BN+ReLU on A ----------------
__global__ void __launch_bounds__(256, 4)
gemm40_kernel(const float* __restrict__ A, const float* __restrict__ W,
              __half* __restrict__ H, int M) {
    __shared__ float As[16][128];
    __shared__ float Bs[16][40];

    int t = threadIdx.x;
    int trow = t >> 3;
    int tcol = t & 7;
    int rowBase = blockIdx.y * 128;

    int arow = t >> 1;
    int acol = (t & 1) * 8;

    float acc[4][5];
#pragma unroll
    for (int i = 0; i < 4; i++)
#pragma unroll
        for (int j = 0; j < 5; j++) acc[i][j] = 0.0f;

    for (int k0 = 0; k0 < 128; k0 += 16) {
        int gr = rowBase + arow;
        float av[8];
        if (gr < M) {
            float4 a0 = *(const float4*)&A[(size_t)gr * 128 + k0 + acol];
            float4 a1 = *(const float4*)&A[(size_t)gr * 128 + k0 + acol + 4];
            av[0] = a0.x; av[1] = a0.y; av[2] = a0.z; av[3] = a0.w;
            av[4] = a1.x; av[5] = a1.y; av[6] = a1.z; av[7] = a1.w;
        } else {
#pragma unroll
            for (int i = 0; i < 8; i++) av[i] = 0.0f;
        }
#pragma unroll
        for (int i = 0; i < 8; i++) {
            int col = k0 + acol + i;
            av[i] = fmaxf(av[i] * g_scale[col] + g_shift[col], 0.0f);
            As[acol + i][arow] = av[i];
        }
        if (t < 160) {
            int brow = t / 10;
            int bcol = (t % 10) * 4;
            *(float4*)&Bs[brow][bcol] = *(const float4*)&W[(size_t)(k0 + brow) * 40 + bcol];
        }
        __syncthreads();

#pragma unroll
        for (int k = 0; k < 16; k++) {
            float a[4], b[5];
            *(float4*)&a[0] = *(const float4*)&As[k][trow * 4];
#pragma unroll
            for (int j = 0; j < 5; j++) b[j] = Bs[k][tcol * 5 + j];
#pragma unroll
            for (int i = 0; i < 4; i++)
#pragma unroll
                for (int j = 0; j < 5; j++) acc[i][j] += a[i] * b[j];
        }
        __syncthreads();
    }

#pragma unroll
    for (int i = 0; i < 4; i++) {
        int gr = rowBase + trow * 4 + i;
        if (gr >= M) continue;
#pragma unroll
        for (int j = 0; j < 5; j++)
            H[(size_t)gr * 40 + tcol * 5 + j] = __float2half_rn(acc[i][j]);
    }
}

// ---------------- aggregate (D=128): warp per node, fp16 gather, packed edges ----------------
__global__ void aggregate128_kernel(const __half* __restrict__ H, float* __restrict__ C,
                                    const float* __restrict__ bias) {
    int warp = (blockIdx.x * blockDim.x + threadIdx.x) >> 5;
    int lane = threadIdx.x & 31;
    if (warp >= NN) return;
    int start = g_rowstart[warp];
    int end   = start + g_cnt[warp];
    const uint2* H2 = (const uint2*)H;   // 4 halves per lane per node
    float4 acc = make_float4(0.f, 0.f, 0.f, 0.f);
    int j = start;
    for (; j + 3 < end; j += 4) {
        int2 e0 = g_edge[j], e1 = g_edge[j + 1], e2 = g_edge[j + 2], e3 = g_edge[j + 3];
        uint2 u0 = H2[(size_t)e0.x * 32 + lane];
        uint2 u1 = H2[(size_t)e1.x * 32 + lane];
        uint2 u2 = H2[(size_t)e2.x * 32 + lane];
        uint2 u3 = H2[(size_t)e3.x * 32 + lane];
        fma_h4(acc, u0, __int_as_float(e0.y));
        fma_h4(acc, u1, __int_as_float(e1.y));
        fma_h4(acc, u2, __int_as_float(e2.y));
        fma_h4(acc, u3, __int_as_float(e3.y));
    }
    for (; j < end; j++) {
        int2 e = g_edge[j];
        fma_h4(acc, H2[(size_t)e.x * 32 + lane], __int_as_float(e.y));
    }
    float di = g_dinv[warp];
    fma_h4(acc, H2[(size_t)warp * 32 + lane], di * di);
    float4 b4 = ((const float4*)bias)[lane];
    ((float4*)C)[(size_t)warp * 32 + lane] =
        make_float4(acc.x + b4.x, acc.y + b4.y, acc.z + b4.z, acc.w + b4.w);
}

// ---------------- BN column stats + prep ----------------
__global__ void colstats_kernel(const float* __restrict__ C) {
    int f  = threadIdx.x;
    int r0 = blockIdx.x * 256;
    int r1 = r0 + 256;
    if (r1 > NN) r1 = NN;
    float s = 0.0f, s2 = 0.0f;
    for (int r = r0; r < r1; r++) {
        float v = C[(size_t)r * DH + f];
        s += v;
        s2 += v * v;
    }
    atomicAdd(&g_colsum[f], s);
    atomicAdd(&g_colsq[f], s2);
}

__global__ void bn_prep_kernel(const float* __restrict__ g, const float* __restrict__ be) {
    int f = threadIdx.x;
    if (f >= DH) return;
    float mu  = g_colsum[f] / (float)NN;
    float var = g_colsq[f] / (float)NN - mu * mu;
    float sc  = g[f] * rsqrtf(var + BN_EPS);
    g_scale[f] = sc;
    g_shift[f] = be[f] - mu * sc;
    g_colsum[f] = 0.0f;
    g_colsq[f]  = 0.0f;
}

// ---------------- layer-3: fp16 aggregate (D=40) + self + bias + log-softmax ----------------
__global__ void aggregate40_softmax_kernel(const __half* __restrict__ H,
                                           const float* __restrict__ bf,
                                           float* __restrict__ out) {
    int warp = (blockIdx.x * blockDim.x + threadIdx.x) >> 5;
    int lane = threadIdx.x & 31;
    if (warp >= NN) return;
    int start = g_rowstart[warp];
    int end   = start + g_cnt[warp];
    if (lane == 0) { g_cnt[warp] = 0; g_fill[warp] = 0; }   // reset for next run
    const uint2* H2 = (const uint2*)H;   // 40 halves = 10 uint2 per node
    bool act = lane < 10;

    float4 acc = make_float4(0.f, 0.f, 0.f, 0.f);
    for (int j = start; j < end; j++) {
        int2 e = g_edge[j];
        if (act) fma_h4(acc, H2[(size_t)e.x * 10 + lane], __int_as_float(e.y));
    }
    float4 v = make_float4(-1e30f, -1e30f, -1e30f, -1e30f);
    if (act) {
        float di = g_dinv[warp];
        fma_h4(acc, H2[(size_t)warp * 10 + lane], di * di);
        float4 b4 = ((const float4*)bf)[lane];
        v = make_float4(acc.x + b4.x, acc.y + b4.y, acc.z + b4.z, acc.w + b4.w);
    }

    float m = fmaxf(fmaxf(v.x, v.y), fmaxf(v.z, v.w));
#pragma unroll
    for (int o = 16; o > 0; o >>= 1) m = fmaxf(m, __shfl_xor_sync(0xffffffffu, m, o));

    float s = 0.0f;
    if (act) s = expf(v.x - m) + expf(v.y - m) + expf(v.z - m) + expf(v.w - m);
#pragma unroll
    for (int o = 16; o > 0; o >>= 1) s += __shfl_xor_sync(0xffffffffu, s, o);

    float ls = m + logf(s);
    if (act) {
        ((float4*)out)[(size_t)warp * 10 + lane] =
            make_float4(v.x - ls, v.y - ls, v.z - ls, v.w - ls);
    }
}

// ---------------- host launch ----------------
extern "C" void kernel_launch(void* const* d_in, const int* in_sizes, int n_in,
                              void* d_out, int out_size) {
    const float* x   = (const float*)d_in[0];
    const int*   ei  = (const int*)d_in[1];    // int32 edge_index
    const float* W1  = (const float*)d_in[2];
    const float* b1  = (const float*)d_in[3];
    const float* g1  = (const float*)d_in[4];
    const float* be1 = (const float*)d_in[5];
    const float* W2  = (const float*)d_in[6];
    const float* b2  = (const float*)d_in[7];
    const float* g2  = (const float*)d_in[8];
    const float* be2 = (const float*)d_in[9];
    const float* Wf  = (const float*)d_in[10];
    const float* bf  = (const float*)d_in[11];
    float* out = (float*)d_out;

    __half* bufH;
    float* bufC;
    cudaGetSymbolAddress((void**)&bufH, g_bufH);
    cudaGetSymbolAddress((void**)&bufC, g_bufC);

    cudaFuncSetAttribute(gemm_mma_kernel<false>, cudaFuncAttributeMaxDynamicSharedMemorySize, SMEM_GEMM_BYTES);
    cudaFuncSetAttribute(gemm_mma_kernel<true>,  cudaFuncAttributeMaxDynamicSharedMemorySize, SMEM_GEMM_BYTES);

    const int T = 256;
    const int nBlocksN = (NN + T - 1) / T;
    const int nBlocksE = (EE + T - 1) / T;
    const int gemmBlocks = (NN + 127) / 128;
    const int warpBlocks = (NN * 32 + T - 1) / T;
    const int statBlocks = (NN + 255) / 256;

    // --- CSR build interleaved with layer-1 GEMM (gemm at launch index 3 -> ncu target) ---
    count_kernel<<<nBlocksE, T>>>(ei);                                 // 0
    scan_block_kernel<<<NBLK, SB>>>();                                 // 1
    scan_bsum_kernel<<<1, 256>>>();                                    // 2
    gemm_mma_kernel<false><<<gemmBlocks, T, SMEM_GEMM_BYTES>>>(x, W1, bufH, NN);  // 3
    scan_finalize_kernel<<<nBlocksN, T>>>();                           // 4
    fill_kernel<<<nBlocksE, T>>>(ei);                                  // 5

    // ---------------- layer 1 (rest) ----------------
    aggregate128_kernel<<<warpBlocks, T>>>(bufH, bufC, b1);            // 6
    colstats_kernel<<<statBlocks, 128>>>(bufC);                        // 7
    bn_prep_kernel<<<1, 128>>>(g1, be1);                               // 8

    // ---------------- layer 2 (BN+ReLU fused into A-load) ----------------
    gemm_mma_kernel<true><<<gemmBlocks, T, SMEM_GEMM_BYTES>>>(bufC, W2, bufH, NN);
    aggregate128_kernel<<<warpBlocks, T>>>(bufH, bufC, b2);
    colstats_kernel<<<statBlocks, 128>>>(bufC);
    bn_prep_kernel<<<1, 128>>>(g2, be2);

    // ---------------- layer 3 ----------------
    gemm40_kernel<<<dim3(1, gemmBlocks), T>>>(bufC, Wf, bufH, NN);
    aggregate40_softmax_kernel<<<warpBlocks, T>>>(bufH, bf, out);
}

// round 16
// speedup vs baseline: 1.5732x; 1.0074x over previous
#include <cuda_runtime.h>
#include <cuda_fp16.h>
#include <math.h>
#include <stdint.h>

#define NN 100000
#define EE 1600000
#define DH 128
#define DOUT 40
#define BN_EPS 1e-5f
#define SB 512
#define NBLK ((NN + SB - 1) / SB)   // 196

// fp16 mma GEMM smem strides (in halves). Stride 136 halves = 68 words,
// 68 % 32 == 4, so the (groupID, tid) fragment-load pattern covers 32
// distinct banks (4*row + tid is a bijection over 8x4).
#define AST2 136
#define BST2 136
#define SMEM_GEMM_BYTES (128 * (AST2 + BST2) * 2)   // 69632

// ---------------- scratch (device globals) ----------------
__device__ __half   g_bufH[(size_t)NN * DH];   // gemm output h (fp16 messages)
__device__ float    g_bufC[(size_t)NN * DH];   // aggregated output (fp32)
__device__ float    g_dinv[NN];
__device__ int      g_cnt[NN];
__device__ int      g_fill[NN];
__device__ int      g_rowstart[NN];
__device__ int      g_incl[NN];
__device__ int      g_bsum[NBLK];
__device__ int      g_boff[NBLK];
__device__ int2     g_edge[EE];                // CSR: (src, edge-norm-as-int) by dst
__device__ float    g_colsum[DH];
__device__ float    g_colsq[DH];
__device__ float    g_scale[DH];
__device__ float    g_shift[DH];

__device__ __forceinline__ void mma_f16(float* d, const uint32_t* a, uint32_t b0, uint32_t b1) {
    asm volatile(
        "mma.sync.aligned.m16n8k16.row.col.f32.f16.f16.f32 "
        "{%0,%1,%2,%3}, {%4,%5,%6,%7}, {%8,%9}, {%0,%1,%2,%3};"
        : "+f"(d[0]), "+f"(d[1]), "+f"(d[2]), "+f"(d[3])
        : "r"(a[0]), "r"(a[1]), "r"(a[2]), "r"(a[3]), "r"(b0), "r"(b1));
}

// unpack 4 halves (uint2) -> 2 float2, fma into float4 acc
__device__ __forceinline__ void fma_h4(float4& acc, uint2 u, float w) {
    __half2* ph = (__half2*)&u;
    float2 f0 = __half22float2(ph[0]);
    float2 f1 = __half22float2(ph[1]);
    acc.x += f0.x * w; acc.y += f0.y * w;
    acc.z += f1.x * w; acc.w += f1.y * w;
}

// ---------------- CSR build (edge_index is int32) ----------------
__global__ void count_kernel(const int* __restrict__ ei) {
    int e = blockIdx.x * blockDim.x + threadIdx.x;
    if (e >= EE) return;
    int d = ei[EE + e];
    if ((unsigned)d < NN) atomicAdd(&g_cnt[d], 1);
}

__global__ void scan_block_kernel() {
    __shared__ int sm[SB];
    int i = blockIdx.x * SB + threadIdx.x;
    int v = (i < NN) ? g_cnt[i] : 0;
    if (i < NN) g_dinv[i] = rsqrtf((float)v + 1.0f);
    sm[threadIdx.x] = v;
    __syncthreads();
#pragma unroll
    for (int off = 1; off < SB; off <<= 1) {
        int t = (threadIdx.x >= off) ? sm[threadIdx.x - off] : 0;
        __syncthreads();
        sm[threadIdx.x] += t;
        __syncthreads();
    }
    if (i < NN) g_incl[i] = sm[threadIdx.x];
    if (threadIdx.x == SB - 1) g_bsum[blockIdx.x] = sm[SB - 1];
}

__global__ void scan_bsum_kernel() {
    __shared__ int sm[256];
    int v = (threadIdx.x < NBLK) ? g_bsum[threadIdx.x] : 0;
    sm[threadIdx.x] = v;
    __syncthreads();
#pragma unroll
    for (int off = 1; off < 256; off <<= 1) {
        int t = (threadIdx.x >= off) ? sm[threadIdx.x - off] : 0;
        __syncthreads();
        sm[threadIdx.x] += t;
        __syncthreads();
    }
    if (threadIdx.x < NBLK) g_boff[threadIdx.x] = sm[threadIdx.x] - v;
}

__global__ void scan_finalize_kernel() {
    int i = blockIdx.x * blockDim.x + threadIdx.x;
    if (i >= NN) return;
    g_rowstart[i] = g_incl[i] + g_boff[i / SB] - g_cnt[i];
}

__global__ void fill_kernel(const int* __restrict__ ei) {
    int e = blockIdx.x * blockDim.x + threadIdx.x;
    if (e >= EE) return;
    int s = ei[e];
    int d = ei[EE + e];
    if ((unsigned)s >= NN || (unsigned)d >= NN) return;
    int pos = g_rowstart[d] + atomicAdd(&g_fill[d], 1);
    g_edge[pos] = make_int2(s, __float_as_int(g_dinv[s] * g_dinv[d]));
}

// ---------------- fp16 mma.sync GEMM: H[M,128] = act(A)[M,128] @ W, fp16 out ----------------
// 256 threads = 8 warps (4 on M x 2 on N); warp computes 32x64 via m16n8k16.
// A fp32 -> fp16 smem row-major [m][k]; W fp32 -> fp16 smem TRANSPOSED [n][k].
template<bool FUSE>
__global__ void __launch_bounds__(256, 2)
gemm_mma_kernel(const float* __restrict__ A, const float* __restrict__ W,
                __half* __restrict__ H, int M) {
    extern __shared__ __half smh[];
    __half* sA = smh;                    // [128][AST2]  (m, k)
    __half* sB = smh + 128 * AST2;       // [128][BST2]  (n, k)

    int t = threadIdx.x;
    int lane = t & 31;
    int wid = t >> 5;
    int warpM = wid & 3;
    int warpN = wid >> 2;
    int rowBase = blockIdx.x * 128;

    // ---- B tile: W[k][n] fp32 -> sB[n][k] fp16 (transpose) ----
    for (int idx = t; idx < 4096; idx += 256) {
        int k  = idx >> 5;          // 0..127
        int n4 = (idx & 31) * 4;    // 0..124
        float4 v = *(const float4*)&W[(size_t)k * 128 + n4];
        sB[(n4 + 0) * BST2 + k] = __float2half_rn(v.x);
        sB[(n4 + 1) * BST2 + k] = __float2half_rn(v.y);
        sB[(n4 + 2) * BST2 + k] = __float2half_rn(v.z);
        sB[(n4 + 3) * BST2 + k] = __float2half_rn(v.w);
    }

    // ---- A tile: row-major load, fp16 convert (+BN/ReLU fuse) ----
    {
        int row  = t >> 1;
        int half = t & 1;
        int gr = rowBase + row;
        const float4* Ar = (const float4*)(A + (size_t)gr * 128 + half * 64);
        __half* dst = sA + row * AST2 + half * 64;
#pragma unroll
        for (int i = 0; i < 16; i++) {
            float4 v = (gr < M) ? Ar[i] : make_float4(0.f, 0.f, 0.f, 0.f);
            if (FUSE) {
                int col = half * 64 + i * 4;
                v.x = fmaxf(v.x * g_scale[col + 0] + g_shift[col + 0], 0.0f);
                v.y = fmaxf(v.y * g_scale[col + 1] + g_shift[col + 1], 0.0f);
                v.z = fmaxf(v.z * g_scale[col + 2] + g_shift[col + 2], 0.0f);
                v.w = fmaxf(v.w * g_scale[col + 3] + g_shift[col + 3], 0.0f);
            }
            __half2 h0 = __floats2half2_rn(v.x, v.y);
            __half2 h1 = __floats2half2_rn(v.z, v.w);
            *(uint2*)(dst + i * 4) =
                make_uint2(*(uint32_t*)&h0, *(uint32_t*)&h1);
        }
    }
    __syncthreads();

    float acc[2][8][4];
#pragma unroll
    for (int mi = 0; mi < 2; mi++)
#pragma unroll
        for (int nj = 0; nj < 8; nj++)
#pragma unroll
            for (int q = 0; q < 4; q++) acc[mi][nj][q] = 0.0f;

    int groupID = lane >> 2;
    int tid4    = lane & 3;
    int arow0 = warpM * 32 + groupID;
    int bn0   = warpN * 64 + groupID;

#pragma unroll
    for (int kc = 0; kc < 8; kc++) {
        int k0 = kc * 16;
        uint32_t a[2][4];
#pragma unroll
        for (int mi = 0; mi < 2; mi++) {
            const __half* p = sA + (arow0 + mi * 16) * AST2 + k0 + tid4 * 2;
            a[mi][0] = *(const uint32_t*)p;
            a[mi][1] = *(const uint32_t*)(p + 8 * AST2);
            a[mi][2] = *(const uint32_t*)(p + 8);
            a[mi][3] = *(const uint32_t*)(p + 8 * AST2 + 8);
        }
#pragma unroll
        for (int nj = 0; nj < 8; nj++) {
            const __half* q = sB + (bn0 + nj * 8) * BST2 + k0 + tid4 * 2;
            uint32_t b0 = *(const uint32_t*)q;
            uint32_t b1 = *(const uint32_t*)(q + 8);
            mma_f16(acc[0][nj], a[0], b0, b1);
            mma_f16(acc[1][nj], a[1], b0, b1);
        }
    }

    // ---- store H as fp16 (same c-fragment layout as m16n8k8) ----
#pragma unroll
    for (int mi = 0; mi < 2; mi++) {
        int r0 = rowBase + warpM * 32 + mi * 16 + groupID;
        int r1 = r0 + 8;
#pragma unroll
        for (int nj = 0; nj < 8; nj++) {
            int col = warpN * 64 + nj * 8 + 2 * tid4;
            if (r0 < M)
                *(__half2*)&H[(size_t)r0 * 128 + col] = __floats2half2_rn(acc[mi][nj][0], acc[mi][nj][1]);
            if (r1 < M)
                *(__half2*)&H[(size_t)r1 * 128 + col] = __floats2half2_rn(acc[mi][nj][2], acc[mi][nj][3]);
        }
    }
}

// ---------------- GEMM 128x40 fp32 compute, fp16 out, fused BN+ReLU on A ----------------
__global__ void __launch_bounds__(256, 4)
gemm40_kernel(const float* __restrict__ A, const float* __restrict__ W,
              __half* __restrict__ H, int M) {
    __shared__ float As[16][128];
    __shared__ float Bs[16][40];

    int t = threadIdx.x;
    int trow = t >> 3;
    int tcol = t & 7;
    int rowBase = blockIdx.y * 128;

    int arow = t >> 1;
    int acol = (t & 1) * 8;

    float acc[4][5];
#pragma unroll
    for (int i = 0; i < 4; i++)
#pragma unroll
        for (int j = 0; j < 5; j++) acc[i][j] = 0.0f;

    for (int k0 = 0; k0 < 128; k0 += 16) {
        int gr = rowBase + arow;
        float av[8];
        if (gr < M) {
            float4 a0 = *(const float4*)&A[(size_t)gr * 128 + k0 + acol];
            float4 a1 = *(const float4*)&A[(size_t)gr * 128 + k0 + acol + 4];
            av[0] = a0.x; av[1] = a0.y; av[2] = a0.z; av[3] = a0.w;
            av[4] = a1.x; av[5] = a1.y; av[6] = a1.z; av[7] = a1.w;
        } else {
#pragma unroll
            for (int i = 0; i < 8; i++) av[i] = 0.0f;
        }
#pragma unroll
        for (int i = 0; i < 8; i++) {
            int col = k0 + acol + i;
            av[i] = fmaxf(av[i] * g_scale[col] + g_shift[col], 0.0f);
            As[acol + i][arow] = av[i];
        }
        if (t < 160) {
            int brow = t / 10;
            int bcol = (t % 10) * 4;
            *(float4*)&Bs[brow][bcol] = *(const float4*)&W[(size_t)(k0 + brow) * 40 + bcol];
        }
        __syncthreads();

#pragma unroll
        for (int k = 0; k < 16; k++) {
            float a[4], b[5];
            *(float4*)&a[0] = *(const float4*)&As[k][trow * 4];
#pragma unroll
            for (int j = 0; j < 5; j++) b[j] = Bs[k][tcol * 5 + j];
#pragma unroll
            for (int i = 0; i < 4; i++)
#pragma unroll
                for (int j = 0; j < 5; j++) acc[i][j] += a[i] * b[j];
        }
        __syncthreads();
    }

#pragma unroll
    for (int i = 0; i < 4; i++) {
        int gr = rowBase + trow * 4 + i;
        if (gr >= M) continue;
#pragma unroll
        for (int j = 0; j < 5; j++)
            H[(size_t)gr * 40 + tcol * 5 + j] = __float2half_rn(acc[i][j]);
    }
}

// ---------------- aggregate (D=128): warp per node, fp16 gather, packed edges ----------------
__global__ void aggregate128_kernel(const __half* __restrict__ H, float* __restrict__ C,
                                    const float* __restrict__ bias) {
    int warp = (blockIdx.x * blockDim.x + threadIdx.x) >> 5;
    int lane = threadIdx.x & 31;
    if (warp >= NN) return;
    int start = g_rowstart[warp];
    int end   = start + g_cnt[warp];
    const uint2* H2 = (const uint2*)H;   // 4 halves per lane per node
    float4 acc = make_float4(0.f, 0.f, 0.f, 0.f);
    int j = start;
    for (; j + 3 < end; j += 4) {
        int2 e0 = g_edge[j], e1 = g_edge[j + 1], e2 = g_edge[j + 2], e3 = g_edge[j + 3];
        uint2 u0 = H2[(size_t)e0.x * 32 + lane];
        uint2 u1 = H2[(size_t)e1.x * 32 + lane];
        uint2 u2 = H2[(size_t)e2.x * 32 + lane];
        uint2 u3 = H2[(size_t)e3.x * 32 + lane];
        fma_h4(acc, u0, __int_as_float(e0.y));
        fma_h4(acc, u1, __int_as_float(e1.y));
        fma_h4(acc, u2, __int_as_float(e2.y));
        fma_h4(acc, u3, __int_as_float(e3.y));
    }
    for (; j < end; j++) {
        int2 e = g_edge[j];
        fma_h4(acc, H2[(size_t)e.x * 32 + lane], __int_as_float(e.y));
    }
    float di = g_dinv[warp];
    fma_h4(acc, H2[(size_t)warp * 32 + lane], di * di);
    float4 b4 = ((const float4*)bias)[lane];
    ((float4*)C)[(size_t)warp * 32 + lane] =
        make_float4(acc.x + b4.x, acc.y + b4.y, acc.z + b4.z, acc.w + b4.w);
}

// ---------------- BN column stats + prep ----------------
__global__ void colstats_kernel(const float* __restrict__ C) {
    int f  = threadIdx.x;
    int r0 = blockIdx.x * 256;
    int r1 = r0 + 256;
    if (r1 > NN) r1 = NN;
    float s = 0.0f, s2 = 0.0f;
    for (int r = r0; r < r1; r++) {
        float v = C[(size_t)r * DH + f];
        s += v;
        s2 += v * v;
    }
    atomicAdd(&g_colsum[f], s);
    atomicAdd(&g_colsq[f], s2);
}

__global__ void bn_prep_kernel(const float* __restrict__ g, const float* __restrict__ be) {
    int f = threadIdx.x;
    if (f >= DH) return;
    float mu  = g_colsum[f] / (float)NN;
    float var = g_colsq[f] / (float)NN - mu * mu;
    float sc  = g[f] * rsqrtf(var + BN_EPS);
    g_scale[f] = sc;
    g_shift[f] = be[f] - mu * sc;
    g_colsum[f] = 0.0f;
    g_colsq[f]  = 0.0f;
}

// ---------------- layer-3: fp16 aggregate (D=40) + self + bias + log-softmax ----------------
__global__ void aggregate40_softmax_kernel(const __half* __restrict__ H,
                                           const float* __restrict__ bf,
                                           float* __restrict__ out) {
    int warp = (blockIdx.x * blockDim.x + threadIdx.x) >> 5;
    int lane = threadIdx.x & 31;
    if (warp >= NN) return;
    int start = g_rowstart[warp];
    int end   = start + g_cnt[warp];
    if (lane == 0) { g_cnt[warp] = 0; g_fill[warp] = 0; }   // reset for next run
    const uint2* H2 = (const uint2*)H;   // 40 halves = 10 uint2 per node
    bool act = lane < 10;

    float4 acc = make_float4(0.f, 0.f, 0.f, 0.f);
    for (int j = start; j < end; j++) {
        int2 e = g_edge[j];
        if (act) fma_h4(acc, H2[(size_t)e.x * 10 + lane], __int_as_float(e.y));
    }
    float4 v = make_float4(-1e30f, -1e30f, -1e30f, -1e30f);
    if (act) {
        float di = g_dinv[warp];
        fma_h4(acc, H2[(size_t)warp * 10 + lane], di * di);
        float4 b4 = ((const float4*)bf)[lane];
        v = make_float4(acc.x + b4.x, acc.y + b4.y, acc.z + b4.z, acc.w + b4.w);
    }

    float m = fmaxf(fmaxf(v.x, v.y), fmaxf(v.z, v.w));
#pragma unroll
    for (int o = 16; o > 0; o >>= 1) m = fmaxf(m, __shfl_xor_sync(0xffffffffu, m, o));

    float s = 0.0f;
    if (act) s = expf(v.x - m) + expf(v.y - m) + expf(v.z - m) + expf(v.w - m);
#pragma unroll
    for (int o = 16; o > 0; o >>= 1) s += __shfl_xor_sync(0xffffffffu, s, o);

    float ls = m + logf(s);
    if (act) {
        ((float4*)out)[(size_t)warp * 10 + lane] =
            make_float4(v.x - ls, v.y - ls, v.z - ls, v.w - ls);
    }
}

// ---------------- host launch ----------------
extern "C" void kernel_launch(void* const* d_in, const int* in_sizes, int n_in,
                              void* d_out, int out_size) {
    const float* x   = (const float*)d_in[0];
    const int*   ei  = (const int*)d_in[1];    // int32 edge_index
    const float* W1  = (const float*)d_in[2];
    const float* b1  = (const float*)d_in[3];
    const float* g1  = (const float*)d_in[4];
    const float* be1 = (const float*)d_in[5];
    const float* W2  = (const float*)d_in[6];
    const float* b2  = (const float*)d_in[7];
    const float* g2  = (const float*)d_in[8];
    const float* be2 = (const float*)d_in[9];
    const float* Wf  = (const float*)d_in[10];
    const float* bf  = (const float*)d_in[11];
    float* out = (float*)d_out;

    __half* bufH;
    float* bufC;
    cudaGetSymbolAddress((void**)&bufH, g_bufH);
    cudaGetSymbolAddress((void**)&bufC, g_bufC);

    cudaFuncSetAttribute(gemm_mma_kernel<false>, cudaFuncAttributeMaxDynamicSharedMemorySize, SMEM_GEMM_BYTES);
    cudaFuncSetAttribute(gemm_mma_kernel<true>,  cudaFuncAttributeMaxDynamicSharedMemorySize, SMEM_GEMM_BYTES);

    const int T = 256;
    const int nBlocksN = (NN + T - 1) / T;
    const int nBlocksE = (EE + T - 1) / T;
    const int gemmBlocks = (NN + 127) / 128;
    const int warpBlocks = (NN * 32 + T - 1) / T;
    const int statBlocks = (NN + 255) / 256;

    // --- CSR build interleaved with layer-1 GEMM (gemm at launch index 3 -> ncu target) ---
    count_kernel<<<nBlocksE, T>>>(ei);                                 // 0
    scan_block_kernel<<<NBLK, SB>>>();                                 // 1
    scan_bsum_kernel<<<1, 256>>>();                                    // 2
    gemm_mma_kernel<false><<<gemmBlocks, T, SMEM_GEMM_BYTES>>>(x, W1, bufH, NN);  // 3
    scan_finalize_kernel<<<nBlocksN, T>>>();                           // 4
    fill_kernel<<<nBlocksE, T>>>(ei);                                  // 5

    // ---------------- layer 1 (rest) ----------------
    aggregate128_kernel<<<warpBlocks, T>>>(bufH, bufC, b1);            // 6
    colstats_kernel<<<statBlocks, 128>>>(bufC);                        // 7
    bn_prep_kernel<<<1, 128>>>(g1, be1);                               // 8

    // ---------------- layer 2 (BN+ReLU fused into A-load) ----------------
    gemm_mma_kernel<true><<<gemmBlocks, T, SMEM_GEMM_BYTES>>>(bufC, W2, bufH, NN);
    aggregate128_kernel<<<warpBlocks, T>>>(bufH, bufC, b2);
    colstats_kernel<<<statBlocks, 128>>>(bufC);
    bn_prep_kernel<<<1, 128>>>(g2, be2);

    // ---------------- layer 3 ----------------
    gemm40_kernel<<<dim3(1, gemmBlocks), T>>>(bufC, Wf, bufH, NN);
    aggregate40_softmax_kernel<<<warpBlocks, T>>>(bufH, bf, out);
}

// round 17
// speedup vs baseline: 1.6633x; 1.0573x over previous
#include <cuda_runtime.h>
#include <cuda_fp16.h>
#include <math.h>
#include <stdint.h>

#define NN 100000
#define EE 1600000
#define DH 128
#define DOUT 40
#define BN_EPS 1e-5f
#define SB 512
#define NBLK ((NN + SB - 1) / SB)   // 196

// fp16 mma GEMM smem strides (in halves). Stride 136 halves = 272 B: an
// 8-row x 16B ldmatrix phase hits banks {4r..4r+3}, r=0..7 -> all 32 banks.
#define AST2 136
#define BST2 136
#define SMEM_GEMM_BYTES (128 * (AST2 + BST2) * 2)   // 69632

// ---------------- scratch (device globals) ----------------
__device__ __half   g_bufH[(size_t)NN * DH];   // gemm output h (fp16 messages)
__device__ float    g_bufC[(size_t)NN * DH];   // aggregated output (fp32)
__device__ __half   g_Wt[2][128 * BST2];       // W1/W2 as fp16, transposed [n][k], padded
__device__ float    g_dinv[NN];
__device__ int      g_cnt[NN];
__device__ int      g_fill[NN];
__device__ int      g_rowstart[NN];
__device__ int      g_incl[NN];
__device__ int      g_bsum[NBLK];
__device__ int      g_boff[NBLK];
__device__ int2     g_edge[EE];                // CSR: (src, edge-norm-as-int) by dst
__device__ float    g_colsum[DH];
__device__ float    g_colsq[DH];
__device__ float    g_scale[DH];
__device__ float    g_shift[DH];

__device__ __forceinline__ void mma_f16(float* d, const uint32_t* a, uint32_t b0, uint32_t b1) {
    asm volatile(
        "mma.sync.aligned.m16n8k16.row.col.f32.f16.f16.f32 "
        "{%0,%1,%2,%3}, {%4,%5,%6,%7}, {%8,%9}, {%0,%1,%2,%3};"
        : "+f"(d[0]), "+f"(d[1]), "+f"(d[2]), "+f"(d[3])
        : "r"(a[0]), "r"(a[1]), "r"(a[2]), "r"(a[3]), "r"(b0), "r"(b1));
}

__device__ __forceinline__ void ldsm4(uint32_t* r, uint32_t addr) {
    asm volatile("ldmatrix.sync.aligned.m8n8.x4.shared.b16 {%0,%1,%2,%3}, [%4];"
                 : "=r"(r[0]), "=r"(r[1]), "=r"(r[2]), "=r"(r[3]) : "r"(addr));
}

// unpack 4 halves (uint2) -> 2 float2, fma into float4 acc
__device__ __forceinline__ void fma_h4(float4& acc, uint2 u, float w) {
    __half2* ph = (__half2*)&u;
    float2 f0 = __half22float2(ph[0]);
    float2 f1 = __half22float2(ph[1]);
    acc.x += f0.x * w; acc.y += f0.y * w;
    acc.z += f1.x * w; acc.w += f1.y * w;
}

// ---------------- W precompute: fp16 transpose [n][k], padded stride ----------------
__global__ void prep_w16_kernel(const float* __restrict__ W1, const float* __restrict__ W2) {
    int idx = blockIdx.x * blockDim.x + threadIdx.x;
    if (idx >= 32768) return;
    int which = idx >> 14;
    int rem = idx & 16383;
    int n = rem >> 7;          // W col
    int k = rem & 127;         // W row (consecutive k -> coalesced writes)
    const float* W = which ? W2 : W1;
    g_Wt[which][n * BST2 + k] = __float2half_rn(W[(size_t)k * 128 + n]);
}

// ---------------- CSR build (edge_index is int32) ----------------
__global__ void count_kernel(const int* __restrict__ ei) {
    int e = blockIdx.x * blockDim.x + threadIdx.x;
    if (e >= EE) return;
    int d = ei[EE + e];
    if ((unsigned)d < NN) atomicAdd(&g_cnt[d], 1);
}

__global__ void scan_block_kernel() {
    __shared__ int sm[SB];
    int i = blockIdx.x * SB + threadIdx.x;
    int v = (i < NN) ? g_cnt[i] : 0;
    if (i < NN) g_dinv[i] = rsqrtf((float)v + 1.0f);
    sm[threadIdx.x] = v;
    __syncthreads();
#pragma unroll
    for (int off = 1; off < SB; off <<= 1) {
        int t = (threadIdx.x >= off) ? sm[threadIdx.x - off] : 0;
        __syncthreads();
        sm[threadIdx.x] += t;
        __syncthreads();
    }
    if (i < NN) g_incl[i] = sm[threadIdx.x];
    if (threadIdx.x == SB - 1) g_bsum[blockIdx.x] = sm[SB - 1];
}

__global__ void scan_bsum_kernel() {
    __shared__ int sm[256];
    int v = (threadIdx.x < NBLK) ? g_bsum[threadIdx.x] : 0;
    sm[threadIdx.x] = v;
    __syncthreads();
#pragma unroll
    for (int off = 1; off < 256; off <<= 1) {
        int t = (threadIdx.x >= off) ? sm[threadIdx.x - off] : 0;
        __syncthreads();
        sm[threadIdx.x] += t;
        __syncthreads();
    }
    if (threadIdx.x < NBLK) g_boff[threadIdx.x] = sm[threadIdx.x] - v;
}

__global__ void scan_finalize_kernel() {
    int i = blockIdx.x * blockDim.x + threadIdx.x;
    if (i >= NN) return;
    g_rowstart[i] = g_incl[i] + g_boff[i / SB] - g_cnt[i];
}

__global__ void fill_kernel(const int* __restrict__ ei) {
    int e = blockIdx.x * blockDim.x + threadIdx.x;
    if (e >= EE) return;
    int s = ei[e];
    int d = ei[EE + e];
    if ((unsigned)s >= NN || (unsigned)d >= NN) return;
    int pos = g_rowstart[d] + atomicAdd(&g_fill[d], 1);
    g_edge[pos] = make_int2(s, __float_as_int(g_dinv[s] * g_dinv[d]));
}

// ---------------- fp16 mma.sync GEMM with ldmatrix ----------------
// H[M,128] = act(A)[M,128] @ W; 256 threads = 8 warps (4 M x 2 N),
// warp computes 32x64 via m16n8k16. A fp32->fp16 smem [m][k];
// Wt pre-transposed fp16 [n][k] copied linearly into smem.
template<bool FUSE>
__global__ void __launch_bounds__(256, 2)
gemm_mma_kernel(const float* __restrict__ A, const __half* __restrict__ Wt,
                __half* __restrict__ H, int M) {
    extern __shared__ __half smh[];
    __half* sA = smh;                    // [128][AST2]  (m, k)
    __half* sB = smh + 128 * AST2;       // [128][BST2]  (n, k)

    int t = threadIdx.x;
    int lane = t & 31;
    int wid = t >> 5;
    int warpM = wid & 3;
    int warpN = wid >> 2;
    int rowBase = blockIdx.x * 128;

    // ---- B tile: linear conflict-free copy of pre-transposed fp16 W ----
    {
        const uint4* g = (const uint4*)Wt;
        uint4* d = (uint4*)sB;
        for (int i = t; i < (128 * BST2) / 8; i += 256) d[i] = g[i];
    }

    // ---- A tile: row-major load, fp16 convert (+BN/ReLU fuse) ----
    {
        int row  = t >> 1;
        int half = t & 1;
        int gr = rowBase + row;
        const float4* Ar = (const float4*)(A + (size_t)gr * 128 + half * 64);
        __half* dst = sA + row * AST2 + half * 64;
#pragma unroll
        for (int i = 0; i < 16; i++) {
            float4 v = (gr < M) ? Ar[i] : make_float4(0.f, 0.f, 0.f, 0.f);
            if (FUSE) {
                int col = half * 64 + i * 4;
                v.x = fmaxf(v.x * g_scale[col + 0] + g_shift[col + 0], 0.0f);
                v.y = fmaxf(v.y * g_scale[col + 1] + g_shift[col + 1], 0.0f);
                v.z = fmaxf(v.z * g_scale[col + 2] + g_shift[col + 2], 0.0f);
                v.w = fmaxf(v.w * g_scale[col + 3] + g_shift[col + 3], 0.0f);
            }
            __half2 h0 = __floats2half2_rn(v.x, v.y);
            __half2 h1 = __floats2half2_rn(v.z, v.w);
            *(uint2*)(dst + i * 4) = make_uint2(*(uint32_t*)&h0, *(uint32_t*)&h1);
        }
    }
    __syncthreads();

    float acc[2][8][4];
#pragma unroll
    for (int mi = 0; mi < 2; mi++)
#pragma unroll
        for (int nj = 0; nj < 8; nj++)
#pragma unroll
            for (int q = 0; q < 4; q++) acc[mi][nj][q] = 0.0f;

    // ldmatrix lane->row mappings
    // A x4: lanes 0-7 T0(rows 0-7,k0), 8-15 T1(rows 8-15,k0),
    //       16-23 T2(rows 0-7,k+8), 24-31 T3(rows 8-15,k+8)
    int aRow = warpM * 32 + (lane & 15);
    int aK   = (lane >> 4) * 8;
    uint32_t saBase = (uint32_t)__cvta_generic_to_shared(sA);
    uint32_t sbBase = (uint32_t)__cvta_generic_to_shared(sB);
    uint32_t addrA0 = saBase + (uint32_t)((aRow)      * AST2 + aK) * 2u;
    uint32_t addrA1 = saBase + (uint32_t)((aRow + 16) * AST2 + aK) * 2u;
    // B x4 covers nj pair (2p, 2p+1): lanes 0-7 (n=2p*8+r, k0), 8-15 (same n, k+8),
    //                                 16-23 (n=(2p+1)*8+r, k0), 24-31 (same, k+8)
    int bN = warpN * 64 + (lane & 7) + ((lane >> 4) << 3);
    int bK = ((lane >> 3) & 1) * 8;
    uint32_t addrB = sbBase + (uint32_t)(bN * BST2 + bK) * 2u;

#pragma unroll
    for (int kc = 0; kc < 8; kc++) {
        uint32_t kadd = (uint32_t)(kc * 16 * 2);
        uint32_t a[2][4];
        ldsm4(a[0], addrA0 + kadd);
        ldsm4(a[1], addrA1 + kadd);
#pragma unroll
        for (int p = 0; p < 4; p++) {
            uint32_t b[4];
            ldsm4(b, addrB + (uint32_t)(p * 16 * BST2 * 2) + kadd);
            mma_f16(acc[0][2 * p],     a[0], b[0], b[1]);
            mma_f16(acc[1][2 * p],     a[1], b[0], b[1]);
            mma_f16(acc[0][2 * p + 1], a[0], b[2], b[3]);
            mma_f16(acc[1][2 * p + 1], a[1], b[2], b[3]);
        }
    }

    // ---- store H as fp16 (canonical c-fragment layout) ----
    int groupID = lane >> 2;
    int tid4    = lane & 3;
#pragma unroll
    for (int mi = 0; mi < 2; mi++) {
        int r0 = rowBase + warpM * 32 + mi * 16 + groupID;
        int r1 = r0 + 8;
#pragma unroll
        for (int nj = 0; nj < 8; nj++) {
            int col = warpN * 64 + nj * 8 + 2 * tid4;
            if (r0 < M)
                *(__half2*)&H[(size_t)r0 * 128 + col] = __floats2half2_rn(acc[mi][nj][0], acc[mi][nj][1]);
            if (r1 < M)
                *(__half2*)&H[(size_t)r1 * 128 + col] = __floats2half2_rn(acc[mi][nj][2], acc[mi][nj][3]);
        }
    }
}

// ---------------- GEMM 128x40 fp32 compute, fp16 out, fused BN+ReLU on A ----------------
__global__ void __launch_bounds__(256, 4)
gemm40_kernel(const float* __restrict__ A, const float* __restrict__ W,
              __half* __restrict__ H, int M) {
    __shared__ float As[16][128];
    __shared__ float Bs[16][40];

    int t = threadIdx.x;
    int trow = t >> 3;
    int tcol = t & 7;
    int rowBase = blockIdx.y * 128;

    int arow = t >> 1;
    int acol = (t & 1) * 8;

    float acc[4][5];
#pragma unroll
    for (int i = 0; i < 4; i++)
#pragma unroll
        for (int j = 0; j < 5; j++) acc[i][j] = 0.0f;

    for (int k0 = 0; k0 < 128; k0 += 16) {
        int gr = rowBase + arow;
        float av[8];
        if (gr < M) {
            float4 a0 = *(const float4*)&A[(size_t)gr * 128 + k0 + acol];
            float4 a1 = *(const float4*)&A[(size_t)gr * 128 + k0 + acol + 4];
            av[0] = a0.x; av[1] = a0.y; av[2] = a0.z; av[3] = a0.w;
            av[4] = a1.x; av[5] = a1.y; av[6] = a1.z; av[7] = a1.w;
        } else {
#pragma unroll
            for (int i = 0; i < 8; i++) av[i] = 0.0f;
        }
#pragma unroll
        for (int i = 0; i < 8; i++) {
            int col = k0 + acol + i;
            av[i] = fmaxf(av[i] * g_scale[col] + g_shift[col], 0.0f);
            As[acol + i][arow] = av[i];
        }
        if (t < 160) {
            int brow = t / 10;
            int bcol = (t % 10) * 4;
            *(float4*)&Bs[brow][bcol] = *(const float4*)&W[(size_t)(k0 + brow) * 40 + bcol];
        }
        __syncthreads();

#pragma unroll
        for (int k = 0; k < 16; k++) {
            float a[4], b[5];
            *(float4*)&a[0] = *(const float4*)&As[k][trow * 4];
#pragma unroll
            for (int j = 0; j < 5; j++) b[j] = Bs[k][tcol * 5 + j];
#pragma unroll
            for (int i = 0; i < 4; i++)
#pragma unroll
                for (int j = 0; j < 5; j++) acc[i][j] += a[i] * b[j];
        }
        __syncthreads();
    }

#pragma unroll
    for (int i = 0; i < 4; i++) {
        int gr = rowBase + trow * 4 + i;
        if (gr >= M) continue;
#pragma unroll
        for (int j = 0; j < 5; j++)
            H[(size_t)gr * 40 + tcol * 5 + j] = __float2half_rn(acc[i][j]);
    }
}

// ---------------- aggregate (D=128): warp per node, fp16 gather, packed edges ----------------
__global__ void aggregate128_kernel(const __half* __restrict__ H, float* __restrict__ C,
                                    const float* __restrict__ bias) {
    int warp = (blockIdx.x * blockDim.x + threadIdx.x) >> 5;
    int lane = threadIdx.x & 31;
    if (warp >= NN) return;
    int start = g_rowstart[warp];
    int end   = start + g_cnt[warp];
    const uint2* H2 = (const uint2*)H;   // 4 halves per lane per node
    float4 acc = make_float4(0.f, 0.f, 0.f, 0.f);
    int j = start;
    for (; j + 3 < end; j += 4) {
        int2 e0 = g_edge[j], e1 = g_edge[j + 1], e2 = g_edge[j + 2], e3 = g_edge[j + 3];
        uint2 u0 = H2[(size_t)e0.x * 32 + lane];
        uint2 u1 = H2[(size_t)e1.x * 32 + lane];
        uint2 u2 = H2[(size_t)e2.x * 32 + lane];
        uint2 u3 = H2[(size_t)e3.x * 32 + lane];
        fma_h4(acc, u0, __int_as_float(e0.y));
        fma_h4(acc, u1, __int_as_float(e1.y));
        fma_h4(acc, u2, __int_as_float(e2.y));
        fma_h4(acc, u3, __int_as_float(e3.y));
    }
    for (; j < end; j++) {
        int2 e = g_edge[j];
        fma_h4(acc, H2[(size_t)e.x * 32 + lane], __int_as_float(e.y));
    }
    float di = g_dinv[warp];
    fma_h4(acc, H2[(size_t)warp * 32 + lane], di * di);
    float4 b4 = ((const float4*)bias)[lane];
    ((float4*)C)[(size_t)warp * 32 + lane] =
        make_float4(acc.x + b4.x, acc.y + b4.y, acc.z + b4.z, acc.w + b4.w);
}

// ---------------- BN column stats + prep ----------------
__global__ void colstats_kernel(const float* __restrict__ C) {
    int f  = threadIdx.x;
    int r0 = blockIdx.x * 256;
    int r1 = r0 + 256;
    if (r1 > NN) r1 = NN;
    float s = 0.0f, s2 = 0.0f;
    for (int r = r0; r < r1; r++) {
        float v = C[(size_t)r * DH + f];
        s += v;
        s2 += v * v;
    }
    atomicAdd(&g_colsum[f], s);
    atomicAdd(&g_colsq[f], s2);
}

__global__ void bn_prep_kernel(const float* __restrict__ g, const float* __restrict__ be) {
    int f = threadIdx.x;
    if (f >= DH) return;
    float mu  = g_colsum[f] / (float)NN;
    float var = g_colsq[f] / (float)NN - mu * mu;
    float sc  = g[f] * rsqrtf(var + BN_EPS);
    g_scale[f] = sc;
    g_shift[f] = be[f] - mu * sc;
    g_colsum[f] = 0.0f;
    g_colsq[f]  = 0.0f;
}

// ---------------- layer-3: fp16 aggregate (D=40) + self + bias + log-softmax ----------------
__global__ void aggregate40_softmax_kernel(const __half* __restrict__ H,
                                           const float* __restrict__ bf,
                                           float* __restrict__ out) {
    int warp = (blockIdx.x * blockDim.x + threadIdx.x) >> 5;
    int lane = threadIdx.x & 31;
    if (warp >= NN) return;
    int start = g_rowstart[warp];
    int end   = start + g_cnt[warp];
    if (lane == 0) { g_cnt[warp] = 0; g_fill[warp] = 0; }   // reset for next run
    const uint2* H2 = (const uint2*)H;   // 40 halves = 10 uint2 per node
    bool act = lane < 10;

    float4 acc = make_float4(0.f, 0.f, 0.f, 0.f);
    for (int j = start; j < end; j++) {
        int2 e = g_edge[j];
        if (act) fma_h4(acc, H2[(size_t)e.x * 10 + lane], __int_as_float(e.y));
    }
    float4 v = make_float4(-1e30f, -1e30f, -1e30f, -1e30f);
    if (act) {
        float di = g_dinv[warp];
        fma_h4(acc, H2[(size_t)warp * 10 + lane], di * di);
        float4 b4 = ((const float4*)bf)[lane];
        v = make_float4(acc.x + b4.x, acc.y + b4.y, acc.z + b4.z, acc.w + b4.w);
    }

    float m = fmaxf(fmaxf(v.x, v.y), fmaxf(v.z, v.w));
#pragma unroll
    for (int o = 16; o > 0; o >>= 1) m = fmaxf(m, __shfl_xor_sync(0xffffffffu, m, o));

    float s = 0.0f;
    if (act) s = expf(v.x - m) + expf(v.y - m) + expf(v.z - m) + expf(v.w - m);
#pragma unroll
    for (int o = 16; o > 0; o >>= 1) s += __shfl_xor_sync(0xffffffffu, s, o);

    float ls = m + logf(s);
    if (act) {
        ((float4*)out)[(size_t)warp * 10 + lane] =
            make_float4(v.x - ls, v.y - ls, v.z - ls, v.w - ls);
    }
}

// ---------------- host launch ----------------
extern "C" void kernel_launch(void* const* d_in, const int* in_sizes, int n_in,
                              void* d_out, int out_size) {
    const float* x   = (const float*)d_in[0];
    const int*   ei  = (const int*)d_in[1];    // int32 edge_index
    const float* W1  = (const float*)d_in[2];
    const float* b1  = (const float*)d_in[3];
    const float* g1  = (const float*)d_in[4];
    const float* be1 = (const float*)d_in[5];
    const float* W2  = (const float*)d_in[6];
    const float* b2  = (const float*)d_in[7];
    const float* g2  = (const float*)d_in[8];
    const float* be2 = (const float*)d_in[9];
    const float* Wf  = (const float*)d_in[10];
    const float* bf  = (const float*)d_in[11];
    float* out = (float*)d_out;

    __half* bufH;
    float* bufC;
    __half* wt;
    cudaGetSymbolAddress((void**)&bufH, g_bufH);
    cudaGetSymbolAddress((void**)&bufC, g_bufC);
    cudaGetSymbolAddress((void**)&wt, g_Wt);

    cudaFuncSetAttribute(gemm_mma_kernel<false>, cudaFuncAttributeMaxDynamicSharedMemorySize, SMEM_GEMM_BYTES);
    cudaFuncSetAttribute(gemm_mma_kernel<true>,  cudaFuncAttributeMaxDynamicSharedMemorySize, SMEM_GEMM_BYTES);

    const int T = 256;
    const int nBlocksN = (NN + T - 1) / T;
    const int nBlocksE = (EE + T - 1) / T;
    const int gemmBlocks = (NN + 127) / 128;
    const int warpBlocks = (NN * 32 + T - 1) / T;
    const int statBlocks = (NN + 255) / 256;

    // --- CSR build interleaved; gemm at launch index 3 -> ncu target ---
    count_kernel<<<nBlocksE, T>>>(ei);                                 // 0
    scan_block_kernel<<<NBLK, SB>>>();                                 // 1
    prep_w16_kernel<<<128, 256>>>(W1, W2);                             // 2
    gemm_mma_kernel<false><<<gemmBlocks, T, SMEM_GEMM_BYTES>>>(x, wt, bufH, NN);  // 3
    scan_bsum_kernel<<<1, 256>>>();                                    // 4
    scan_finalize_kernel<<<nBlocksN, T>>>();                           // 5
    fill_kernel<<<nBlocksE, T>>>(ei);                                  // 6

    // ---------------- layer 1 (rest) ----------------
    aggregate128_kernel<<<warpBlocks, T>>>(bufH, bufC, b1);
    colstats_kernel<<<statBlocks, 128>>>(bufC);
    bn_prep_kernel<<<1, 128>>>(g1, be1);

    // ---------------- layer 2 (BN+ReLU fused into A-load) ----------------
    gemm_mma_kernel<true><<<gemmBlocks, T, SMEM_GEMM_BYTES>>>(bufC, wt + 128 * BST2, bufH, NN);
    aggregate128_kernel<<<warpBlocks, T>>>(bufH, bufC, b2);
    colstats_kernel<<<statBlocks, 128>>>(bufC);
    bn_prep_kernel<<<1, 128>>>(g2, be2);

    // ---------------- layer 3 ----------------
    gemm40_kernel<<<dim3(1, gemmBlocks), T>>>(bufC, Wf, bufH, NN);
    aggregate40_softmax_kernel<<<warpBlocks, T>>>(bufH, bf, out);
}